// round 10
// baseline (speedup 1.0000x reference)
#include <cuda_runtime.h>
#include <cuda_fp16.h>
#include <math.h>
#include <stdint.h>

#define BATCH 2
#define NSEQ  2048
#define DMODEL 2048
#define HEADS 16
#define DHEAD 128
#define ROWS (BATCH*NSEQ)   // 4096

// ---------------------------------------------------------------------------
// scratch (device globals: no allocation allowed)
// ---------------------------------------------------------------------------
__device__ __half g_xhi[ROWS*DMODEL];
__device__ __half g_xlo[ROWS*DMODEL];
__device__ __half g_ahi[ROWS*DMODEL];
__device__ __half g_alo[ROWS*DMODEL];
__device__ __half g_qh[ROWS*DMODEL];
__device__ __half g_ql[ROWS*DMODEL];
__device__ __half g_kh[ROWS*DMODEL];
__device__ __half g_vh[ROWS*DMODEL];
__device__ __half g_wq[DMODEL*DMODEL];
__device__ __half g_wk[DMODEL*DMODEL];
__device__ __half g_wv[DMODEL*DMODEL];
__device__ __half g_wo[DMODEL*DMODEL];

// ---------------------------------------------------------------------------
// helpers
// ---------------------------------------------------------------------------
__device__ __forceinline__ uint32_t smem_u32(const void* p) {
    uint32_t a;
    asm("{ .reg .u64 t; cvta.to.shared.u64 t, %1; cvt.u32.u64 %0, t; }" : "=r"(a) : "l"(p));
    return a;
}

__device__ __forceinline__ void cp16(uint32_t dst, const void* src) {
    asm volatile("cp.async.cg.shared.global [%0], [%1], 16;" :: "r"(dst), "l"(src));
}
#define CP_COMMIT() asm volatile("cp.async.commit_group;" ::: "memory")
#define CP_WAIT(n)  asm volatile("cp.async.wait_group %0;" :: "n"(n) : "memory")

__device__ __forceinline__ void ldmx4(uint32_t addr, uint32_t& r0, uint32_t& r1,
                                      uint32_t& r2, uint32_t& r3) {
    asm volatile("ldmatrix.sync.aligned.m8n8.x4.shared.b16 {%0,%1,%2,%3}, [%4];"
                 : "=r"(r0), "=r"(r1), "=r"(r2), "=r"(r3) : "r"(addr));
}
__device__ __forceinline__ void ldmx4t(uint32_t addr, uint32_t& r0, uint32_t& r1,
                                       uint32_t& r2, uint32_t& r3) {
    asm volatile("ldmatrix.sync.aligned.m8n8.x4.trans.shared.b16 {%0,%1,%2,%3}, [%4];"
                 : "=r"(r0), "=r"(r1), "=r"(r2), "=r"(r3) : "r"(addr));
}

// fp16 inputs, fp32 accumulate
__device__ __forceinline__ void mma16816(float& c0, float& c1, float& c2, float& c3,
                                         uint32_t a0, uint32_t a1, uint32_t a2, uint32_t a3,
                                         uint32_t b0, uint32_t b1) {
    asm volatile(
        "mma.sync.aligned.m16n8k16.row.col.f32.f16.f16.f32 "
        "{%0,%1,%2,%3}, {%4,%5,%6,%7}, {%8,%9}, {%0,%1,%2,%3};"
        : "+f"(c0), "+f"(c1), "+f"(c2), "+f"(c3)
        : "r"(a0), "r"(a1), "r"(a2), "r"(a3), "r"(b0), "r"(b1));
}

// fp16 inputs, fp16 accumulate (2x issue rate on fp32-acc-half-rate parts)
__device__ __forceinline__ void mma16816h(uint32_t& d0, uint32_t& d1,
                                          uint32_t a0, uint32_t a1, uint32_t a2, uint32_t a3,
                                          uint32_t b0, uint32_t b1) {
    asm volatile(
        "mma.sync.aligned.m16n8k16.row.col.f16.f16.f16.f16 "
        "{%0,%1}, {%2,%3,%4,%5}, {%6,%7}, {%0,%1};"
        : "+r"(d0), "+r"(d1)
        : "r"(a0), "r"(a1), "r"(a2), "r"(a3), "r"(b0), "r"(b1));
}

__device__ __forceinline__ uint32_t packh(float a, float b) {
    __half2 t = __floats2half2_rn(a, b);
    return *(uint32_t*)&t;
}

// ---------------------------------------------------------------------------
// split: fp32 -> (hi, lo) fp16 pair
// ---------------------------------------------------------------------------
__global__ __launch_bounds__(256)
void split_kernel(const float4* __restrict__ in, __half* __restrict__ hi,
                  __half* __restrict__ lo, int n4)
{
    int i = blockIdx.x * 256 + threadIdx.x;
    if (i >= n4) return;
    float4 v = in[i];
    __half h0 = __float2half(v.x);
    __half h1 = __float2half(v.y);
    __half h2 = __float2half(v.z);
    __half h3 = __float2half(v.w);
    __half2* hp = (__half2*)(hi + 4 * (size_t)i);
    hp[0] = __half2(h0, h1);
    hp[1] = __half2(h2, h3);
    __half2* lp = (__half2*)(lo + 4 * (size_t)i);
    lp[0] = __half2(__float2half(v.x - __half2float(h0)),
                    __float2half(v.y - __half2float(h1)));
    lp[1] = __half2(__float2half(v.z - __half2float(h2)),
                    __float2half(v.w - __half2float(h3)));
}

// ---------------------------------------------------------------------------
// transpose + convert: W[K][N] fp32 -> Wt[N][K] fp16 (hi only), 4 weights
// ---------------------------------------------------------------------------
__global__ __launch_bounds__(256)
void transpose_cvt4(const float* __restrict__ W0, const float* __restrict__ W1,
                    const float* __restrict__ W2, const float* __restrict__ W3,
                    __half* __restrict__ t0, __half* __restrict__ t1,
                    __half* __restrict__ t2, __half* __restrict__ t3)
{
    int z = blockIdx.z;
    const float* W = (z == 0) ? W0 : (z == 1) ? W1 : (z == 2) ? W2 : W3;
    __half* th = (z == 0) ? t0 : (z == 1) ? t1 : (z == 2) ? t2 : t3;

    __shared__ float t[32][33];
    int n0 = blockIdx.x * 32, k0 = blockIdx.y * 32;
    int tx = threadIdx.x & 31, ty = threadIdx.x >> 5;
#pragma unroll
    for (int i = 0; i < 32; i += 8)
        t[ty + i][tx] = W[(size_t)(k0 + ty + i) * DMODEL + n0 + tx];
    __syncthreads();
#pragma unroll
    for (int i = 0; i < 32; i += 8)
        th[(size_t)(n0 + ty + i) * DMODEL + k0 + tx] = __float2half(t[tx][ty + i]);
}

// ---------------------------------------------------------------------------
// GEMM config: hi-pass fp32-acc + lo-pass fp16-acc.
// CTA 128x128, 512 threads (16 warps, warp tile 32x32), KC=64, double-buffered.
// ---------------------------------------------------------------------------
#define GK DMODEL
#define TM 128
#define TN 128
#define KC 64
#define RSTRB 144u                    // bytes per smem row (128 data + 16 pad)
#define TILE_B (128u * RSTRB)         // 18432
#define STAGE_B (3u * TILE_B)         // 55296 (Ah, Al, Bh)
#define GEMM_SMEM (2u * STAGE_B)      // 110592

// mainloop: warp (wm 0..3 row-block of 32, wn 0..3 col-block of 32)
#define GEMM_MAINLOOP(ACC, ACCL)                                                        \
    const int NCH = GK / KC;                                                            \
    copy_chunk(0, 0);                                                                   \
    const uint32_t lrow = (uint32_t)(lane & 15);                                        \
    const uint32_t lcol2 = (uint32_t)((lane >> 4) & 1) * 16u;                           \
    for (int c = 0; c < NCH; c++) {                                                     \
        int stg = c & 1;                                                                \
        if (c + 1 < NCH) {                                                              \
            copy_chunk(c + 1, stg ^ 1);                                                 \
            CP_WAIT(1);                                                                 \
        } else {                                                                        \
            CP_WAIT(0);                                                                 \
        }                                                                               \
        __syncthreads();                                                                \
        uint32_t base = sb + (uint32_t)stg * STAGE_B;                                   \
        uint32_t ah_b = base;                                                           \
        uint32_t al_b = base + TILE_B;                                                  \
        uint32_t bh_b = base + 2u * TILE_B;                                             \
        _Pragma("unroll")                                                               \
        for (int kk = 0; kk < 4; kk++) {                                                \
            uint32_t koff = (uint32_t)kk * 32u + lcol2;                                 \
            uint32_t Ah[2][4], Al[2][4];                                                \
            _Pragma("unroll")                                                           \
            for (int mi = 0; mi < 2; mi++) {                                            \
                uint32_t roff = ((uint32_t)(wm * 32 + mi * 16) + lrow) * RSTRB + koff;  \
                ldmx4(ah_b + roff, Ah[mi][0], Ah[mi][1], Ah[mi][2], Ah[mi][3]);         \
                ldmx4(al_b + roff, Al[mi][0], Al[mi][1], Al[mi][2], Al[mi][3]);         \
            }                                                                           \
            uint32_t Bh[4][2];                                                          \
            _Pragma("unroll")                                                           \
            for (int np = 0; np < 2; np++) {                                            \
                uint32_t roff = ((uint32_t)(wn * 32 + np * 16) + lrow) * RSTRB + koff;  \
                uint32_t r0, r1, r2, r3;                                                \
                ldmx4(bh_b + roff, r0, r1, r2, r3);                                     \
                Bh[np * 2][0] = r0; Bh[np * 2 + 1][0] = r1;                             \
                Bh[np * 2][1] = r2; Bh[np * 2 + 1][1] = r3;                             \
            }                                                                           \
            _Pragma("unroll")                                                           \
            for (int mi = 0; mi < 2; mi++)                                              \
                _Pragma("unroll")                                                       \
                for (int ni = 0; ni < 4; ni++) {                                        \
                    mma16816(ACC[mi][ni][0], ACC[mi][ni][1], ACC[mi][ni][2], ACC[mi][ni][3], \
                             Ah[mi][0], Ah[mi][1], Ah[mi][2], Ah[mi][3],                \
                             Bh[ni][0], Bh[ni][1]);                                     \
                    mma16816h(ACCL[mi][ni][0], ACCL[mi][ni][1],                         \
                              Al[mi][0], Al[mi][1], Al[mi][2], Al[mi][3],               \
                              Bh[ni][0], Bh[ni][1]);                                    \
                }                                                                       \
        }                                                                               \
        __syncthreads();                                                                \
    }                                                                                   \
    _Pragma("unroll")                                                                   \
    for (int mi = 0; mi < 2; mi++)                                                      \
        _Pragma("unroll")                                                               \
        for (int ni = 0; ni < 4; ni++) {                                                \
            __half2 p0 = *(__half2*)&ACCL[mi][ni][0];                                   \
            __half2 p1 = *(__half2*)&ACCL[mi][ni][1];                                   \
            ACC[mi][ni][0] += __low2float(p0);  ACC[mi][ni][1] += __high2float(p0);     \
            ACC[mi][ni][2] += __low2float(p1);  ACC[mi][ni][3] += __high2float(p1);     \
        }

#define GEMM_COPY_CHUNK                                                                 \
    auto copy_chunk = [&](int c, int stg) {                                             \
        int k0 = c * KC;                                                                \
        uint32_t base = sb + (uint32_t)stg * STAGE_B;                                   \
        const __half* srcs[3] = { Ahi, Alo, Bhh };                                      \
        int rows0[3] = { brow, brow, bcol };                                            \
        _Pragma("unroll")                                                               \
        for (int t = 0; t < 3; t++) {                                                   \
            const __half* src = srcs[t] + (size_t)rows0[t] * GK + k0;                   \
            uint32_t tb = base + (uint32_t)t * TILE_B;                                  \
            _Pragma("unroll")                                                           \
            for (int i = 0; i < 2; i++) {                                               \
                int s = i * 512 + tid;                                                  \
                int r = s >> 3, seg = s & 7;                                            \
                cp16(tb + (uint32_t)r * RSTRB + (uint32_t)seg * 16u,                    \
                     src + (size_t)r * GK + seg * 8);                                   \
            }                                                                           \
        }                                                                               \
        CP_COMMIT();                                                                    \
    };

#define GEMM_ACC_DECL                                                                   \
    float acc[2][4][4];                                                                 \
    uint32_t accl[2][4][2];                                                             \
    _Pragma("unroll")                                                                   \
    for (int i = 0; i < 2; i++)                                                         \
        _Pragma("unroll")                                                               \
        for (int j = 0; j < 4; j++) {                                                   \
            _Pragma("unroll")                                                           \
            for (int r = 0; r < 4; r++) acc[i][j][r] = 0.f;                             \
            accl[i][j][0] = 0u; accl[i][j][1] = 0u;                                     \
        }

// ---------------------------------------------------------------------------
// Fused QKV GEMM + rotary + fp16 split epilogue. grid (48, 32), 512 threads.
// ---------------------------------------------------------------------------
__global__ __launch_bounds__(512, 1)
void gemm_qkv(const __half* __restrict__ xhi, const __half* __restrict__ xlo,
              const __half* __restrict__ wq, const __half* __restrict__ wk,
              const __half* __restrict__ wv,
              const float* __restrict__ bq, const float* __restrict__ bk,
              const float* __restrict__ bv,
              __half* __restrict__ qh, __half* __restrict__ ql,
              __half* __restrict__ kh, __half* __restrict__ vh)
{
    extern __shared__ __align__(128) char smem[];
    uint32_t sb = smem_u32(smem);
    const int tid  = threadIdx.x;
    const int wid  = tid >> 5;
    const int lane = tid & 31;
    const int brow = blockIdx.y * TM;
    const int mtx  = blockIdx.x >> 4;            // 0=q, 1=k, 2=v
    const int bcol = (blockIdx.x & 15) * TN;

    const __half* Ahi = xhi;
    const __half* Alo = xlo;
    const __half* Bhh = (mtx == 0) ? wq : (mtx == 1) ? wk : wv;
    const float* bias = (mtx == 0) ? bq : (mtx == 1) ? bk : bv;

    const int wm = wid & 3;
    const int wn = wid >> 2;

    GEMM_ACC_DECL
    GEMM_COPY_CHUNK
    GEMM_MAINLOOP(acc, accl)

    // ------ fused epilogue: stage fp32 tile in smem, rotary+split, store ----
    float* ft = (float*)smem;    // [128][132] fp32 = 67584 B
    int g = lane >> 2, t4 = lane & 3;
#pragma unroll
    for (int mi = 0; mi < 2; mi++) {
        int r0 = wm * 32 + mi * 16 + g;
#pragma unroll
        for (int ni = 0; ni < 4; ni++) {
            int cl = wn * 32 + ni * 8 + 2 * t4;
            float2 b01 = *(const float2*)&bias[bcol + cl];
            *(float2*)&ft[r0 * 132 + cl] =
                make_float2(acc[mi][ni][0] + b01.x, acc[mi][ni][1] + b01.y);
            *(float2*)&ft[(r0 + 8) * 132 + cl] =
                make_float2(acc[mi][ni][2] + b01.x, acc[mi][ni][3] + b01.y);
        }
    }
    __syncthreads();

    const bool  do_rot = (mtx < 2);
    const float scale  = (mtx == 0) ? 0.08838834764831845f : 1.0f;
    int d  = tid & 63;
    int rb = tid >> 6;   // 0..7
    float inv_freq = __expf(-(float)d * (9.210340371976184f / 64.0f));

    for (int rr = rb; rr < 128; rr += 8) {
        int grow = brow + rr;
        float a = ft[rr * 132 + d];
        float b2 = ft[rr * 132 + d + 64];
        float oa, ob2;
        if (do_rot) {
            int n = grow & (NSEQ - 1);
            float s, c;
            sincosf((float)n * inv_freq, &s, &c);
            oa  = (a * c - b2 * s) * scale;
            ob2 = (b2 * c + a * s) * scale;
        } else {
            oa = a; ob2 = b2;
        }
        size_t base = (size_t)grow * DMODEL + bcol + d;
        if (mtx == 0) {
            __half h = __float2half(oa);
            qh[base] = h;
            ql[base] = __float2half(oa - __half2float(h));
            h = __float2half(ob2);
            qh[base + 64] = h;
            ql[base + 64] = __float2half(ob2 - __half2float(h));
        } else {
            __half* Oh = (mtx == 1) ? kh : vh;
            Oh[base]      = __float2half(oa);
            Oh[base + 64] = __float2half(ob2);
        }
    }
}

// ---------------------------------------------------------------------------
// GEMM, fp32 output + bias — out projection. 512 threads.
// ---------------------------------------------------------------------------
__global__ __launch_bounds__(512, 1)
void gemm_2p(const __half* __restrict__ Ahi, const __half* __restrict__ Alo,
             const __half* __restrict__ Bhh,
             const float* __restrict__ bias, float* __restrict__ C)
{
    extern __shared__ __align__(128) char smem[];
    uint32_t sb = smem_u32(smem);
    const int tid  = threadIdx.x;
    const int wid  = tid >> 5;
    const int lane = tid & 31;
    const int brow = blockIdx.y * TM;
    const int bcol = blockIdx.x * TN;

    const int wm = wid & 3;
    const int wn = wid >> 2;

    GEMM_ACC_DECL
    GEMM_COPY_CHUNK
    GEMM_MAINLOOP(acc, accl)

    int g = lane >> 2, t4 = lane & 3;
#pragma unroll
    for (int mi = 0; mi < 2; mi++) {
        int r0 = brow + wm * 32 + mi * 16 + g;
#pragma unroll
        for (int ni = 0; ni < 4; ni++) {
            int col = bcol + wn * 32 + ni * 8 + 2 * t4;
            float2 b01 = *(const float2*)&bias[col];
            float2 o0, o1;
            o0.x = acc[mi][ni][0] + b01.x;
            o0.y = acc[mi][ni][1] + b01.y;
            o1.x = acc[mi][ni][2] + b01.x;
            o1.y = acc[mi][ni][3] + b01.y;
            *(float2*)&C[(size_t)r0 * DMODEL + col]       = o0;
            *(float2*)&C[(size_t)(r0 + 8) * DMODEL + col] = o1;
        }
    }
}

// ---------------------------------------------------------------------------
// Flash attention (causal), fp16 2-pass: S=(Qh+Ql)Kh, O=(Ph+Pl)Vh.
// BR=BC=64, 128 threads, Q in regs, 4 rotating buffers — unchanged from R9.
// ---------------------------------------------------------------------------
#define ABUF_B 17408u
#define ATT_SMEM (4u * ABUF_B)        // 69632

__global__ __launch_bounds__(128)
void flash_attn_mma(const __half* __restrict__ qh, const __half* __restrict__ ql,
                    const __half* __restrict__ kh, const __half* __restrict__ vh,
                    __half* __restrict__ oh, __half* __restrict__ ol)
{
    extern __shared__ __align__(128) char smem[];
    uint32_t sb = smem_u32(smem);

    const int tid  = threadIdx.x;
    const int warp = tid >> 5;
    const int lane = tid & 31;
    const int g    = lane >> 2;
    const int q4   = lane & 3;

    const int it = gridDim.x - 1 - blockIdx.x;   // heavy tiles first
    const int bh = blockIdx.y;
    const int b = bh >> 4, h = bh & 15;
    const int i0 = it * 64;

    const size_t hoff = (size_t)b * NSEQ * DMODEL + h * DHEAD;
    const __half* qhb = qh + hoff;
    const __half* qlb = ql + hoff;
    const __half* khb = kh + hoff;
    const __half* vhb = vh + hoff;

    auto copyTile = [&](const __half* src, int row0, uint32_t buf) {
#pragma unroll
        for (int i = 0; i < 8; i++) {
            int s = i * 128 + tid;
            int r = s >> 4, seg = s & 15;
            cp16(buf + (uint32_t)r * 272u + (uint32_t)seg * 16u,
                 src + (size_t)(row0 + r) * DMODEL + seg * 8);
        }
    };

    uint32_t K0 = sb, K1 = sb + ABUF_B, V0 = sb + 2u * ABUF_B, V1 = sb + 3u * ABUF_B;

    copyTile(qhb, i0, K1);
    copyTile(qlb, i0, V1);
    CP_COMMIT();
    copyTile(khb, 0, K0);
    copyTile(vhb, 0, V0);
    CP_COMMIT();

    CP_WAIT(1);
    __syncthreads();

    const uint32_t lrow = (uint32_t)(lane & 15);
    const uint32_t lseg16 = (uint32_t)(lane >> 4) * 16u;
    uint32_t Qh4[8][4], Ql4[8][4];
#pragma unroll
    for (int kk = 0; kk < 8; kk++) {
        uint32_t qoff = ((uint32_t)(warp * 16) + lrow) * 272u + lseg16 + (uint32_t)kk * 32u;
        ldmx4(K1 + qoff, Qh4[kk][0], Qh4[kk][1], Qh4[kk][2], Qh4[kk][3]);
        ldmx4(V1 + qoff, Ql4[kk][0], Ql4[kk][1], Ql4[kk][2], Ql4[kk][3]);
    }

    float m0 = -1e30f, m1 = -1e30f, l0 = 0.f, l1 = 0.f;
    float oa[16][4];
#pragma unroll
    for (int d = 0; d < 16; d++)
#pragma unroll
        for (int r = 0; r < 4; r++) oa[d][r] = 0.f;

    const int NJT = it + 1;

    for (int jt = 0; jt < NJT; jt++) {
        int stg = jt & 1;
        uint32_t kb = stg ? K1 : K0;
        uint32_t vb = stg ? V1 : V0;

        CP_WAIT(0);
        __syncthreads();
        if (jt + 1 < NJT) {
            copyTile(khb, (jt + 1) * 64, stg ? K0 : K1);
            copyTile(vhb, (jt + 1) * 64, stg ? V0 : V1);
            CP_COMMIT();
        }

        float s[8][4];
#pragma unroll
        for (int nb = 0; nb < 8; nb++)
#pragma unroll
            for (int r = 0; r < 4; r++) s[nb][r] = 0.f;

#pragma unroll
        for (int kk = 0; kk < 8; kk++) {
#pragma unroll
            for (int np = 0; np < 4; np++) {
                uint32_t koff = ((uint32_t)(np * 16) + lrow) * 272u + lseg16 + (uint32_t)kk * 32u;
                uint32_t h0, h1, h2, h3;
                ldmx4(kb + koff, h0, h1, h2, h3);
                int nb = np * 2;
                mma16816(s[nb][0], s[nb][1], s[nb][2], s[nb][3],
                         Qh4[kk][0], Qh4[kk][1], Qh4[kk][2], Qh4[kk][3], h0, h2);
                mma16816(s[nb][0], s[nb][1], s[nb][2], s[nb][3],
                         Ql4[kk][0], Ql4[kk][1], Ql4[kk][2], Ql4[kk][3], h0, h2);
                mma16816(s[nb + 1][0], s[nb + 1][1], s[nb + 1][2], s[nb + 1][3],
                         Qh4[kk][0], Qh4[kk][1], Qh4[kk][2], Qh4[kk][3], h1, h3);
                mma16816(s[nb + 1][0], s[nb + 1][1], s[nb + 1][2], s[nb + 1][3],
                         Ql4[kk][0], Ql4[kk][1], Ql4[kk][2], Ql4[kk][3], h1, h3);
            }
        }

        if (jt == it) {
            int r0 = warp * 16 + g;
            int r1 = r0 + 8;
#pragma unroll
            for (int nb = 0; nb < 8; nb++) {
                int c0 = nb * 8 + 2 * q4;
                if (c0 > r0)     s[nb][0] = -1e30f;
                if (c0 + 1 > r0) s[nb][1] = -1e30f;
                if (c0 > r1)     s[nb][2] = -1e30f;
                if (c0 + 1 > r1) s[nb][3] = -1e30f;
            }
        }

        float mx0 = -1e30f, mx1 = -1e30f;
#pragma unroll
        for (int nb = 0; nb < 8; nb++) {
            mx0 = fmaxf(mx0, fmaxf(s[nb][0], s[nb][1]));
            mx1 = fmaxf(mx1, fmaxf(s[nb][2], s[nb][3]));
        }
        mx0 = fmaxf(mx0, __shfl_xor_sync(0xffffffffu, mx0, 1));
        mx0 = fmaxf(mx0, __shfl_xor_sync(0xffffffffu, mx0, 2));
        mx1 = fmaxf(mx1, __shfl_xor_sync(0xffffffffu, mx1, 1));
        mx1 = fmaxf(mx1, __shfl_xor_sync(0xffffffffu, mx1, 2));

        float m0n = fmaxf(m0, mx0), m1n = fmaxf(m1, mx1);
        float f0 = __expf(m0 - m0n), f1 = __expf(m1 - m1n);

        float sum0 = 0.f, sum1 = 0.f;
#pragma unroll
        for (int nb = 0; nb < 8; nb++) {
            s[nb][0] = __expf(s[nb][0] - m0n);
            s[nb][1] = __expf(s[nb][1] - m0n);
            s[nb][2] = __expf(s[nb][2] - m1n);
            s[nb][3] = __expf(s[nb][3] - m1n);
            sum0 += s[nb][0] + s[nb][1];
            sum1 += s[nb][2] + s[nb][3];
        }
        sum0 += __shfl_xor_sync(0xffffffffu, sum0, 1);
        sum0 += __shfl_xor_sync(0xffffffffu, sum0, 2);
        sum1 += __shfl_xor_sync(0xffffffffu, sum1, 1);
        sum1 += __shfl_xor_sync(0xffffffffu, sum1, 2);

        m0 = m0n; m1 = m1n;
        l0 = l0 * f0 + sum0;
        l1 = l1 * f1 + sum1;

#pragma unroll
        for (int d = 0; d < 16; d++) {
            oa[d][0] *= f0; oa[d][1] *= f0;
            oa[d][2] *= f1; oa[d][3] *= f1;
        }

        uint32_t Ph[4][4], Pl[4][4];
#pragma unroll
        for (int kk2 = 0; kk2 < 4; kk2++) {
            int nb = 2 * kk2;
#pragma unroll
            for (int half = 0; half < 2; half++) {
                int src = nb + half;
                float p0 = s[src][0], p1 = s[src][1], p2 = s[src][2], p3 = s[src][3];
                __half2 hA = __floats2half2_rn(p0, p1);
                __half2 hB = __floats2half2_rn(p2, p3);
                Ph[kk2][half * 2 + 0] = *(uint32_t*)&hA;
                Ph[kk2][half * 2 + 1] = *(uint32_t*)&hB;
                Pl[kk2][half * 2 + 0] = packh(p0 - __half2float(__low2half(hA)),
                                              p1 - __half2float(__high2half(hA)));
                Pl[kk2][half * 2 + 1] = packh(p2 - __half2float(__low2half(hB)),
                                              p3 - __half2float(__high2half(hB)));
            }
        }

#pragma unroll
        for (int kk2 = 0; kk2 < 4; kk2++) {
#pragma unroll
            for (int dp = 0; dp < 8; dp++) {
                uint32_t voff = ((uint32_t)(kk2 * 16) + lrow) * 272u
                              + (uint32_t)dp * 32u + lseg16;
                uint32_t h0, h1, h2, h3;
                ldmx4t(vb + voff, h0, h1, h2, h3);
                int dnb = dp * 2;
                mma16816(oa[dnb][0], oa[dnb][1], oa[dnb][2], oa[dnb][3],
                         Ph[kk2][0], Ph[kk2][1], Ph[kk2][2], Ph[kk2][3], h0, h1);
                mma16816(oa[dnb][0], oa[dnb][1], oa[dnb][2], oa[dnb][3],
                         Pl[kk2][0], Pl[kk2][1], Pl[kk2][2], Pl[kk2][3], h0, h1);
                mma16816(oa[dnb + 1][0], oa[dnb + 1][1], oa[dnb + 1][2], oa[dnb + 1][3],
                         Ph[kk2][0], Ph[kk2][1], Ph[kk2][2], Ph[kk2][3], h2, h3);
                mma16816(oa[dnb + 1][0], oa[dnb + 1][1], oa[dnb + 1][2], oa[dnb + 1][3],
                         Pl[kk2][0], Pl[kk2][1], Pl[kk2][2], Pl[kk2][3], h2, h3);
            }
        }
    }

    float inv0 = 1.0f / l0, inv1 = 1.0f / l1;
    int r0 = i0 + warp * 16 + g;
    __half* ohb = oh + hoff;
    __half* olb = ol + hoff;
#pragma unroll
    for (int dnb = 0; dnb < 16; dnb++) {
        int col = dnb * 8 + 2 * q4;
        float a0 = oa[dnb][0] * inv0, a1 = oa[dnb][1] * inv0;
        float b0f = oa[dnb][2] * inv1, b1f = oa[dnb][3] * inv1;
        __half2 h0 = __floats2half2_rn(a0, a1);
        __half2 h1 = __floats2half2_rn(b0f, b1f);
        *(__half2*)&ohb[(size_t)r0 * DMODEL + col] = h0;
        *(__half2*)&ohb[(size_t)(r0 + 8) * DMODEL + col] = h1;
        __half2 lo0 = __floats2half2_rn(a0 - __half2float(__low2half(h0)),
                                        a1 - __half2float(__high2half(h0)));
        __half2 lo1 = __floats2half2_rn(b0f - __half2float(__low2half(h1)),
                                        b1f - __half2float(__high2half(h1)));
        *(__half2*)&olb[(size_t)r0 * DMODEL + col] = lo0;
        *(__half2*)&olb[(size_t)(r0 + 8) * DMODEL + col] = lo1;
    }
}

// ---------------------------------------------------------------------------
extern "C" void kernel_launch(void* const* d_in, const int* in_sizes, int n_in,
                              void* d_out, int out_size)
{
    const float* x  = (const float*)d_in[0];
    const float* Wq = (const float*)d_in[1];
    const float* bq = (const float*)d_in[2];
    const float* Wk = (const float*)d_in[3];
    const float* bk = (const float*)d_in[4];
    const float* Wv = (const float*)d_in[5];
    const float* bv = (const float*)d_in[6];
    const float* Wo = (const float*)d_in[7];
    const float* bo = (const float*)d_in[8];
    float* out = (float*)d_out;

    __half *xhi, *xlo, *ahi, *alo, *qhh, *qll, *khh, *vhh;
    __half *wq, *wk, *wv, *wo;
    cudaGetSymbolAddress((void**)&xhi, g_xhi);
    cudaGetSymbolAddress((void**)&xlo, g_xlo);
    cudaGetSymbolAddress((void**)&ahi, g_ahi);
    cudaGetSymbolAddress((void**)&alo, g_alo);
    cudaGetSymbolAddress((void**)&qhh, g_qh);
    cudaGetSymbolAddress((void**)&qll, g_ql);
    cudaGetSymbolAddress((void**)&khh, g_kh);
    cudaGetSymbolAddress((void**)&vhh, g_vh);
    cudaGetSymbolAddress((void**)&wq, g_wq);
    cudaGetSymbolAddress((void**)&wk, g_wk);
    cudaGetSymbolAddress((void**)&wv, g_wv);
    cudaGetSymbolAddress((void**)&wo, g_wo);

    cudaFuncSetAttribute(gemm_qkv, cudaFuncAttributeMaxDynamicSharedMemorySize, GEMM_SMEM);
    cudaFuncSetAttribute(gemm_2p, cudaFuncAttributeMaxDynamicSharedMemorySize, GEMM_SMEM);
    cudaFuncSetAttribute(flash_attn_mma, cudaFuncAttributeMaxDynamicSharedMemorySize, ATT_SMEM);

    // prep
    int n4x = ROWS * DMODEL / 4;
    split_kernel<<<(n4x + 255) / 256, 256>>>((const float4*)x, xhi, xlo, n4x);
    dim3 tgrid(DMODEL / 32, DMODEL / 32, 4);
    transpose_cvt4<<<tgrid, 256>>>(Wq, Wk, Wv, Wo, wq, wk, wv, wo);

    // fused QKV projection + rotary + split
    dim3 qkv_grid(3 * DMODEL / TN, ROWS / TM);   // (48, 32)
    gemm_qkv<<<qkv_grid, 512, GEMM_SMEM>>>(xhi, xlo, wq, wk, wv,
                                           bq, bk, bv, qhh, qll, khh, vhh);

    // tensor-core flash attention
    dim3 attn_grid(NSEQ / 64, BATCH * HEADS);   // (32, 32)
    flash_attn_mma<<<attn_grid, 128, ATT_SMEM>>>(qhh, qll, khh, vhh, ahi, alo);

    // output projection
    dim3 ggrid(DMODEL / TN, ROWS / TM);   // (16, 32)
    gemm_2p<<<ggrid, 512, GEMM_SMEM>>>(ahi, alo, wo, bo, out);
}

// round 11
// speedup vs baseline: 1.4153x; 1.4153x over previous
#include <cuda_runtime.h>
#include <cuda_fp16.h>
#include <math.h>
#include <stdint.h>

#define BATCH 2
#define NSEQ  2048
#define DMODEL 2048
#define HEADS 16
#define DHEAD 128
#define ROWS (BATCH*NSEQ)   // 4096

// ---------------------------------------------------------------------------
// scratch (device globals: no allocation allowed)
// ---------------------------------------------------------------------------
__device__ __half g_xhi[ROWS*DMODEL];
__device__ __half g_ahi[ROWS*DMODEL];
__device__ __half g_alo[ROWS*DMODEL];
__device__ __half g_qh[ROWS*DMODEL];
__device__ __half g_ql[ROWS*DMODEL];
__device__ __half g_kh[ROWS*DMODEL];
__device__ __half g_vh[ROWS*DMODEL];
__device__ __half g_wq[DMODEL*DMODEL];
__device__ __half g_wk[DMODEL*DMODEL];
__device__ __half g_wv[DMODEL*DMODEL];
__device__ __half g_wo[DMODEL*DMODEL];

// ---------------------------------------------------------------------------
// helpers
// ---------------------------------------------------------------------------
__device__ __forceinline__ uint32_t smem_u32(const void* p) {
    uint32_t a;
    asm("{ .reg .u64 t; cvta.to.shared.u64 t, %1; cvt.u32.u64 %0, t; }" : "=r"(a) : "l"(p));
    return a;
}

__device__ __forceinline__ void cp16(uint32_t dst, const void* src) {
    asm volatile("cp.async.cg.shared.global [%0], [%1], 16;" :: "r"(dst), "l"(src));
}
#define CP_COMMIT() asm volatile("cp.async.commit_group;" ::: "memory")
#define CP_WAIT(n)  asm volatile("cp.async.wait_group %0;" :: "n"(n) : "memory")

__device__ __forceinline__ void ldmx4(uint32_t addr, uint32_t& r0, uint32_t& r1,
                                      uint32_t& r2, uint32_t& r3) {
    asm volatile("ldmatrix.sync.aligned.m8n8.x4.shared.b16 {%0,%1,%2,%3}, [%4];"
                 : "=r"(r0), "=r"(r1), "=r"(r2), "=r"(r3) : "r"(addr));
}
__device__ __forceinline__ void ldmx4t(uint32_t addr, uint32_t& r0, uint32_t& r1,
                                       uint32_t& r2, uint32_t& r3) {
    asm volatile("ldmatrix.sync.aligned.m8n8.x4.trans.shared.b16 {%0,%1,%2,%3}, [%4];"
                 : "=r"(r0), "=r"(r1), "=r"(r2), "=r"(r3) : "r"(addr));
}

// fp16 inputs, fp32 accumulate
__device__ __forceinline__ void mma16816(float& c0, float& c1, float& c2, float& c3,
                                         uint32_t a0, uint32_t a1, uint32_t a2, uint32_t a3,
                                         uint32_t b0, uint32_t b1) {
    asm volatile(
        "mma.sync.aligned.m16n8k16.row.col.f32.f16.f16.f32 "
        "{%0,%1,%2,%3}, {%4,%5,%6,%7}, {%8,%9}, {%0,%1,%2,%3};"
        : "+f"(c0), "+f"(c1), "+f"(c2), "+f"(c3)
        : "r"(a0), "r"(a1), "r"(a2), "r"(a3), "r"(b0), "r"(b1));
}

__device__ __forceinline__ uint32_t packh(float a, float b) {
    __half2 t = __floats2half2_rn(a, b);
    return *(uint32_t*)&t;
}

// ---------------------------------------------------------------------------
// convert: fp32 -> fp16 (hi only)
// ---------------------------------------------------------------------------
__global__ __launch_bounds__(256)
void cvt_kernel(const float4* __restrict__ in, __half* __restrict__ hi, int n4)
{
    int i = blockIdx.x * 256 + threadIdx.x;
    if (i >= n4) return;
    float4 v = in[i];
    __half2* hp = (__half2*)(hi + 4 * (size_t)i);
    hp[0] = __floats2half2_rn(v.x, v.y);
    hp[1] = __floats2half2_rn(v.z, v.w);
}

// ---------------------------------------------------------------------------
// transpose + convert: W[K][N] fp32 -> Wt[N][K] fp16 (hi only), 4 weights
// ---------------------------------------------------------------------------
__global__ __launch_bounds__(256)
void transpose_cvt4(const float* __restrict__ W0, const float* __restrict__ W1,
                    const float* __restrict__ W2, const float* __restrict__ W3,
                    __half* __restrict__ t0, __half* __restrict__ t1,
                    __half* __restrict__ t2, __half* __restrict__ t3)
{
    int z = blockIdx.z;
    const float* W = (z == 0) ? W0 : (z == 1) ? W1 : (z == 2) ? W2 : W3;
    __half* th = (z == 0) ? t0 : (z == 1) ? t1 : (z == 2) ? t2 : t3;

    __shared__ float t[32][33];
    int n0 = blockIdx.x * 32, k0 = blockIdx.y * 32;
    int tx = threadIdx.x & 31, ty = threadIdx.x >> 5;
#pragma unroll
    for (int i = 0; i < 32; i += 8)
        t[ty + i][tx] = W[(size_t)(k0 + ty + i) * DMODEL + n0 + tx];
    __syncthreads();
#pragma unroll
    for (int i = 0; i < 32; i += 8)
        th[(size_t)(n0 + ty + i) * DMODEL + k0 + tx] = __float2half(t[tx][ty + i]);
}

// ---------------------------------------------------------------------------
// GEMM config (R9 shape): CTA 128x128, 256 threads, warp tile 64x32, KC=64
// ---------------------------------------------------------------------------
#define GK DMODEL
#define TM 128
#define TN 128
#define KC 64
#define RSTRB 144u                     // bytes per smem row (128 data + 16 pad)
#define TILE_B (128u * RSTRB)          // 18432
#define STAGE1_B (2u * TILE_B)         // 36864  (Ah, Bh)   single-pass
#define STAGE2_B (3u * TILE_B)         // 55296  (Ah, Al, Bh) two-pass
#define QKV_SMEM (2u * STAGE1_B)       // 73728
#define OUT_SMEM (2u * STAGE2_B)       // 110592

// ---------------------------------------------------------------------------
// Fused QKV GEMM (SINGLE pass: x hi only) + rotary + fp16 split epilogue.
// grid (48, 32): blockIdx.x = mtx*16 + head-column.
// ---------------------------------------------------------------------------
__global__ __launch_bounds__(256, 2)
void gemm_qkv(const __half* __restrict__ xhi,
              const __half* __restrict__ wq, const __half* __restrict__ wk,
              const __half* __restrict__ wv,
              const float* __restrict__ bq, const float* __restrict__ bk,
              const float* __restrict__ bv,
              __half* __restrict__ qh, __half* __restrict__ ql,
              __half* __restrict__ kh, __half* __restrict__ vh)
{
    extern __shared__ __align__(128) char smem[];
    uint32_t sb = smem_u32(smem);
    const int tid  = threadIdx.x;
    const int wid  = tid >> 5;
    const int lane = tid & 31;
    const int brow = blockIdx.y * TM;
    const int mtx  = blockIdx.x >> 4;            // 0=q, 1=k, 2=v
    const int bcol = (blockIdx.x & 15) * TN;

    const __half* Bhh = (mtx == 0) ? wq : (mtx == 1) ? wk : wv;
    const float* bias = (mtx == 0) ? bq : (mtx == 1) ? bk : bv;

    const int wm = wid & 1;    // 2 m-blocks of 64
    const int wn = wid >> 1;   // 4 n-blocks of 32

    float acc[4][4][4];
#pragma unroll
    for (int i = 0; i < 4; i++)
#pragma unroll
        for (int j = 0; j < 4; j++)
#pragma unroll
            for (int r = 0; r < 4; r++) acc[i][j][r] = 0.f;

    auto copy_chunk = [&](int c, int stg) {
        int k0 = c * KC;
        uint32_t base = sb + (uint32_t)stg * STAGE1_B;
        const __half* srcs[2] = { xhi, Bhh };
        int rows0[2] = { brow, bcol };
#pragma unroll
        for (int t = 0; t < 2; t++) {
            const __half* src = srcs[t] + (size_t)rows0[t] * GK + k0;
            uint32_t tb = base + (uint32_t)t * TILE_B;
#pragma unroll
            for (int i = 0; i < 4; i++) {
                int s = i * 256 + tid;
                int r = s >> 3, seg = s & 7;
                cp16(tb + (uint32_t)r * RSTRB + (uint32_t)seg * 16u,
                     src + (size_t)r * GK + seg * 8);
            }
        }
        CP_COMMIT();
    };

    const int NCH = GK / KC;
    copy_chunk(0, 0);
    const uint32_t lrow = (uint32_t)(lane & 15);
    const uint32_t lcol2 = (uint32_t)((lane >> 4) & 1) * 16u;

    for (int c = 0; c < NCH; c++) {
        int stg = c & 1;
        if (c + 1 < NCH) {
            copy_chunk(c + 1, stg ^ 1);
            CP_WAIT(1);
        } else {
            CP_WAIT(0);
        }
        __syncthreads();
        uint32_t base = sb + (uint32_t)stg * STAGE1_B;
        uint32_t ah_b = base;
        uint32_t bh_b = base + TILE_B;
#pragma unroll
        for (int kk = 0; kk < 4; kk++) {
            uint32_t koff = (uint32_t)kk * 32u + lcol2;
            uint32_t Ah[4][4];
#pragma unroll
            for (int mi = 0; mi < 4; mi++) {
                uint32_t roff = ((uint32_t)(wm * 64 + mi * 16) + lrow) * RSTRB + koff;
                ldmx4(ah_b + roff, Ah[mi][0], Ah[mi][1], Ah[mi][2], Ah[mi][3]);
            }
            uint32_t Bh[4][2];
#pragma unroll
            for (int np = 0; np < 2; np++) {
                uint32_t roff = ((uint32_t)(wn * 32 + np * 16) + lrow) * RSTRB + koff;
                uint32_t r0, r1, r2, r3;
                ldmx4(bh_b + roff, r0, r1, r2, r3);
                Bh[np * 2][0] = r0; Bh[np * 2 + 1][0] = r1;
                Bh[np * 2][1] = r2; Bh[np * 2 + 1][1] = r3;
            }
#pragma unroll
            for (int mi = 0; mi < 4; mi++)
#pragma unroll
                for (int ni = 0; ni < 4; ni++)
                    mma16816(acc[mi][ni][0], acc[mi][ni][1], acc[mi][ni][2], acc[mi][ni][3],
                             Ah[mi][0], Ah[mi][1], Ah[mi][2], Ah[mi][3],
                             Bh[ni][0], Bh[ni][1]);
        }
        __syncthreads();
    }

    // ------ fused epilogue: stage fp32 tile in smem, rotary+split, store ----
    float* ft = (float*)smem;    // [128][132] fp32 = 67584 B (< 73728)
    int g = lane >> 2, t4 = lane & 3;
#pragma unroll
    for (int mi = 0; mi < 4; mi++) {
        int r0 = wm * 64 + mi * 16 + g;
#pragma unroll
        for (int ni = 0; ni < 4; ni++) {
            int cl = wn * 32 + ni * 8 + 2 * t4;
            float2 b01 = *(const float2*)&bias[bcol + cl];
            *(float2*)&ft[r0 * 132 + cl] =
                make_float2(acc[mi][ni][0] + b01.x, acc[mi][ni][1] + b01.y);
            *(float2*)&ft[(r0 + 8) * 132 + cl] =
                make_float2(acc[mi][ni][2] + b01.x, acc[mi][ni][3] + b01.y);
        }
    }
    __syncthreads();

    const bool  do_rot = (mtx < 2);
    const float scale  = (mtx == 0) ? 0.08838834764831845f : 1.0f;
    int d  = tid & 63;
    int rb = tid >> 6;
    float inv_freq = __expf(-(float)d * (9.210340371976184f / 64.0f));

    for (int rr = rb; rr < 128; rr += 4) {
        int grow = brow + rr;
        float a = ft[rr * 132 + d];
        float b2 = ft[rr * 132 + d + 64];
        float oa, ob2;
        if (do_rot) {
            int n = grow & (NSEQ - 1);
            float s, c;
            sincosf((float)n * inv_freq, &s, &c);
            oa  = (a * c - b2 * s) * scale;
            ob2 = (b2 * c + a * s) * scale;
        } else {
            oa = a; ob2 = b2;
        }
        size_t base = (size_t)grow * DMODEL + bcol + d;
        if (mtx == 0) {
            __half h = __float2half(oa);
            qh[base] = h;
            ql[base] = __float2half(oa - __half2float(h));
            h = __float2half(ob2);
            qh[base + 64] = h;
            ql[base + 64] = __float2half(ob2 - __half2float(h));
        } else {
            __half* Oh = (mtx == 1) ? kh : vh;
            Oh[base]      = __float2half(oa);
            Oh[base + 64] = __float2half(ob2);
        }
    }
}

// ---------------------------------------------------------------------------
// Out projection GEMM (TWO pass: a hi+lo), fp32 output + bias — R9 shape
// ---------------------------------------------------------------------------
__global__ __launch_bounds__(256, 2)
void gemm_2p(const __half* __restrict__ Ahi, const __half* __restrict__ Alo,
             const __half* __restrict__ Bhh,
             const float* __restrict__ bias, float* __restrict__ C)
{
    extern __shared__ __align__(128) char smem[];
    uint32_t sb = smem_u32(smem);
    const int tid  = threadIdx.x;
    const int wid  = tid >> 5;
    const int lane = tid & 31;
    const int brow = blockIdx.y * TM;
    const int bcol = blockIdx.x * TN;

    const int wm = wid & 1;
    const int wn = wid >> 1;

    float acc[4][4][4];
#pragma unroll
    for (int i = 0; i < 4; i++)
#pragma unroll
        for (int j = 0; j < 4; j++)
#pragma unroll
            for (int r = 0; r < 4; r++) acc[i][j][r] = 0.f;

    auto copy_chunk = [&](int c, int stg) {
        int k0 = c * KC;
        uint32_t base = sb + (uint32_t)stg * STAGE2_B;
        const __half* srcs[3] = { Ahi, Alo, Bhh };
        int rows0[3] = { brow, brow, bcol };
#pragma unroll
        for (int t = 0; t < 3; t++) {
            const __half* src = srcs[t] + (size_t)rows0[t] * GK + k0;
            uint32_t tb = base + (uint32_t)t * TILE_B;
#pragma unroll
            for (int i = 0; i < 4; i++) {
                int s = i * 256 + tid;
                int r = s >> 3, seg = s & 7;
                cp16(tb + (uint32_t)r * RSTRB + (uint32_t)seg * 16u,
                     src + (size_t)r * GK + seg * 8);
            }
        }
        CP_COMMIT();
    };

    const int NCH = GK / KC;
    copy_chunk(0, 0);
    const uint32_t lrow = (uint32_t)(lane & 15);
    const uint32_t lcol2 = (uint32_t)((lane >> 4) & 1) * 16u;

    for (int c = 0; c < NCH; c++) {
        int stg = c & 1;
        if (c + 1 < NCH) {
            copy_chunk(c + 1, stg ^ 1);
            CP_WAIT(1);
        } else {
            CP_WAIT(0);
        }
        __syncthreads();
        uint32_t base = sb + (uint32_t)stg * STAGE2_B;
        uint32_t ah_b = base;
        uint32_t al_b = base + TILE_B;
        uint32_t bh_b = base + 2u * TILE_B;
#pragma unroll
        for (int kk = 0; kk < 4; kk++) {
            uint32_t koff = (uint32_t)kk * 32u + lcol2;
            uint32_t Ah[4][4], Al[4][4];
#pragma unroll
            for (int mi = 0; mi < 4; mi++) {
                uint32_t roff = ((uint32_t)(wm * 64 + mi * 16) + lrow) * RSTRB + koff;
                ldmx4(ah_b + roff, Ah[mi][0], Ah[mi][1], Ah[mi][2], Ah[mi][3]);
                ldmx4(al_b + roff, Al[mi][0], Al[mi][1], Al[mi][2], Al[mi][3]);
            }
            uint32_t Bh[4][2];
#pragma unroll
            for (int np = 0; np < 2; np++) {
                uint32_t roff = ((uint32_t)(wn * 32 + np * 16) + lrow) * RSTRB + koff;
                uint32_t r0, r1, r2, r3;
                ldmx4(bh_b + roff, r0, r1, r2, r3);
                Bh[np * 2][0] = r0; Bh[np * 2 + 1][0] = r1;
                Bh[np * 2][1] = r2; Bh[np * 2 + 1][1] = r3;
            }
#pragma unroll
            for (int mi = 0; mi < 4; mi++)
#pragma unroll
                for (int ni = 0; ni < 4; ni++) {
                    mma16816(acc[mi][ni][0], acc[mi][ni][1], acc[mi][ni][2], acc[mi][ni][3],
                             Ah[mi][0], Ah[mi][1], Ah[mi][2], Ah[mi][3],
                             Bh[ni][0], Bh[ni][1]);
                    mma16816(acc[mi][ni][0], acc[mi][ni][1], acc[mi][ni][2], acc[mi][ni][3],
                             Al[mi][0], Al[mi][1], Al[mi][2], Al[mi][3],
                             Bh[ni][0], Bh[ni][1]);
                }
        }
        __syncthreads();
    }

    int g = lane >> 2, t4 = lane & 3;
#pragma unroll
    for (int mi = 0; mi < 4; mi++) {
        int r0 = brow + wm * 64 + mi * 16 + g;
#pragma unroll
        for (int ni = 0; ni < 4; ni++) {
            int col = bcol + wn * 32 + ni * 8 + 2 * t4;
            float2 b01 = *(const float2*)&bias[col];
            float2 o0, o1;
            o0.x = acc[mi][ni][0] + b01.x;
            o0.y = acc[mi][ni][1] + b01.y;
            o1.x = acc[mi][ni][2] + b01.x;
            o1.y = acc[mi][ni][3] + b01.y;
            *(float2*)&C[(size_t)r0 * DMODEL + col]       = o0;
            *(float2*)&C[(size_t)(r0 + 8) * DMODEL + col] = o1;
        }
    }
}

// ---------------------------------------------------------------------------
// Flash attention (causal), fp16 2-pass: S=(Qh+Ql)Kh, O=(Ph+Pl)Vh.
// BR=BC=64, 128 threads, Q in regs, 4 rotating buffers — R9 verbatim.
// ---------------------------------------------------------------------------
#define ABUF_B 17408u
#define ATT_SMEM (4u * ABUF_B)        // 69632

__global__ __launch_bounds__(128)
void flash_attn_mma(const __half* __restrict__ qh, const __half* __restrict__ ql,
                    const __half* __restrict__ kh, const __half* __restrict__ vh,
                    __half* __restrict__ oh, __half* __restrict__ ol)
{
    extern __shared__ __align__(128) char smem[];
    uint32_t sb = smem_u32(smem);

    const int tid  = threadIdx.x;
    const int warp = tid >> 5;
    const int lane = tid & 31;
    const int g    = lane >> 2;
    const int q4   = lane & 3;

    const int it = gridDim.x - 1 - blockIdx.x;   // heavy tiles first
    const int bh = blockIdx.y;
    const int b = bh >> 4, h = bh & 15;
    const int i0 = it * 64;

    const size_t hoff = (size_t)b * NSEQ * DMODEL + h * DHEAD;
    const __half* qhb = qh + hoff;
    const __half* qlb = ql + hoff;
    const __half* khb = kh + hoff;
    const __half* vhb = vh + hoff;

    auto copyTile = [&](const __half* src, int row0, uint32_t buf) {
#pragma unroll
        for (int i = 0; i < 8; i++) {
            int s = i * 128 + tid;
            int r = s >> 4, seg = s & 15;
            cp16(buf + (uint32_t)r * 272u + (uint32_t)seg * 16u,
                 src + (size_t)(row0 + r) * DMODEL + seg * 8);
        }
    };

    uint32_t K0 = sb, K1 = sb + ABUF_B, V0 = sb + 2u * ABUF_B, V1 = sb + 3u * ABUF_B;

    copyTile(qhb, i0, K1);
    copyTile(qlb, i0, V1);
    CP_COMMIT();
    copyTile(khb, 0, K0);
    copyTile(vhb, 0, V0);
    CP_COMMIT();

    CP_WAIT(1);
    __syncthreads();

    const uint32_t lrow = (uint32_t)(lane & 15);
    const uint32_t lseg16 = (uint32_t)(lane >> 4) * 16u;
    uint32_t Qh4[8][4], Ql4[8][4];
#pragma unroll
    for (int kk = 0; kk < 8; kk++) {
        uint32_t qoff = ((uint32_t)(warp * 16) + lrow) * 272u + lseg16 + (uint32_t)kk * 32u;
        ldmx4(K1 + qoff, Qh4[kk][0], Qh4[kk][1], Qh4[kk][2], Qh4[kk][3]);
        ldmx4(V1 + qoff, Ql4[kk][0], Ql4[kk][1], Ql4[kk][2], Ql4[kk][3]);
    }

    float m0 = -1e30f, m1 = -1e30f, l0 = 0.f, l1 = 0.f;
    float oa[16][4];
#pragma unroll
    for (int d = 0; d < 16; d++)
#pragma unroll
        for (int r = 0; r < 4; r++) oa[d][r] = 0.f;

    const int NJT = it + 1;

    for (int jt = 0; jt < NJT; jt++) {
        int stg = jt & 1;
        uint32_t kb = stg ? K1 : K0;
        uint32_t vb = stg ? V1 : V0;

        CP_WAIT(0);
        __syncthreads();
        if (jt + 1 < NJT) {
            copyTile(khb, (jt + 1) * 64, stg ? K0 : K1);
            copyTile(vhb, (jt + 1) * 64, stg ? V0 : V1);
            CP_COMMIT();
        }

        float s[8][4];
#pragma unroll
        for (int nb = 0; nb < 8; nb++)
#pragma unroll
            for (int r = 0; r < 4; r++) s[nb][r] = 0.f;

#pragma unroll
        for (int kk = 0; kk < 8; kk++) {
#pragma unroll
            for (int np = 0; np < 4; np++) {
                uint32_t koff = ((uint32_t)(np * 16) + lrow) * 272u + lseg16 + (uint32_t)kk * 32u;
                uint32_t h0, h1, h2, h3;
                ldmx4(kb + koff, h0, h1, h2, h3);
                int nb = np * 2;
                mma16816(s[nb][0], s[nb][1], s[nb][2], s[nb][3],
                         Qh4[kk][0], Qh4[kk][1], Qh4[kk][2], Qh4[kk][3], h0, h2);
                mma16816(s[nb][0], s[nb][1], s[nb][2], s[nb][3],
                         Ql4[kk][0], Ql4[kk][1], Ql4[kk][2], Ql4[kk][3], h0, h2);
                mma16816(s[nb + 1][0], s[nb + 1][1], s[nb + 1][2], s[nb + 1][3],
                         Qh4[kk][0], Qh4[kk][1], Qh4[kk][2], Qh4[kk][3], h1, h3);
                mma16816(s[nb + 1][0], s[nb + 1][1], s[nb + 1][2], s[nb + 1][3],
                         Ql4[kk][0], Ql4[kk][1], Ql4[kk][2], Ql4[kk][3], h1, h3);
            }
        }

        if (jt == it) {
            int r0 = warp * 16 + g;
            int r1 = r0 + 8;
#pragma unroll
            for (int nb = 0; nb < 8; nb++) {
                int c0 = nb * 8 + 2 * q4;
                if (c0 > r0)     s[nb][0] = -1e30f;
                if (c0 + 1 > r0) s[nb][1] = -1e30f;
                if (c0 > r1)     s[nb][2] = -1e30f;
                if (c0 + 1 > r1) s[nb][3] = -1e30f;
            }
        }

        float mx0 = -1e30f, mx1 = -1e30f;
#pragma unroll
        for (int nb = 0; nb < 8; nb++) {
            mx0 = fmaxf(mx0, fmaxf(s[nb][0], s[nb][1]));
            mx1 = fmaxf(mx1, fmaxf(s[nb][2], s[nb][3]));
        }
        mx0 = fmaxf(mx0, __shfl_xor_sync(0xffffffffu, mx0, 1));
        mx0 = fmaxf(mx0, __shfl_xor_sync(0xffffffffu, mx0, 2));
        mx1 = fmaxf(mx1, __shfl_xor_sync(0xffffffffu, mx1, 1));
        mx1 = fmaxf(mx1, __shfl_xor_sync(0xffffffffu, mx1, 2));

        float m0n = fmaxf(m0, mx0), m1n = fmaxf(m1, mx1);
        float f0 = __expf(m0 - m0n), f1 = __expf(m1 - m1n);

        float sum0 = 0.f, sum1 = 0.f;
#pragma unroll
        for (int nb = 0; nb < 8; nb++) {
            s[nb][0] = __expf(s[nb][0] - m0n);
            s[nb][1] = __expf(s[nb][1] - m0n);
            s[nb][2] = __expf(s[nb][2] - m1n);
            s[nb][3] = __expf(s[nb][3] - m1n);
            sum0 += s[nb][0] + s[nb][1];
            sum1 += s[nb][2] + s[nb][3];
        }
        sum0 += __shfl_xor_sync(0xffffffffu, sum0, 1);
        sum0 += __shfl_xor_sync(0xffffffffu, sum0, 2);
        sum1 += __shfl_xor_sync(0xffffffffu, sum1, 1);
        sum1 += __shfl_xor_sync(0xffffffffu, sum1, 2);

        m0 = m0n; m1 = m1n;
        l0 = l0 * f0 + sum0;
        l1 = l1 * f1 + sum1;

#pragma unroll
        for (int d = 0; d < 16; d++) {
            oa[d][0] *= f0; oa[d][1] *= f0;
            oa[d][2] *= f1; oa[d][3] *= f1;
        }

        uint32_t Ph[4][4], Pl[4][4];
#pragma unroll
        for (int kk2 = 0; kk2 < 4; kk2++) {
            int nb = 2 * kk2;
#pragma unroll
            for (int half = 0; half < 2; half++) {
                int src = nb + half;
                float p0 = s[src][0], p1 = s[src][1], p2 = s[src][2], p3 = s[src][3];
                __half2 hA = __floats2half2_rn(p0, p1);
                __half2 hB = __floats2half2_rn(p2, p3);
                Ph[kk2][half * 2 + 0] = *(uint32_t*)&hA;
                Ph[kk2][half * 2 + 1] = *(uint32_t*)&hB;
                Pl[kk2][half * 2 + 0] = packh(p0 - __half2float(__low2half(hA)),
                                              p1 - __half2float(__high2half(hA)));
                Pl[kk2][half * 2 + 1] = packh(p2 - __half2float(__low2half(hB)),
                                              p3 - __half2float(__high2half(hB)));
            }
        }

#pragma unroll
        for (int kk2 = 0; kk2 < 4; kk2++) {
#pragma unroll
            for (int dp = 0; dp < 8; dp++) {
                uint32_t voff = ((uint32_t)(kk2 * 16) + lrow) * 272u
                              + (uint32_t)dp * 32u + lseg16;
                uint32_t h0, h1, h2, h3;
                ldmx4t(vb + voff, h0, h1, h2, h3);
                int dnb = dp * 2;
                mma16816(oa[dnb][0], oa[dnb][1], oa[dnb][2], oa[dnb][3],
                         Ph[kk2][0], Ph[kk2][1], Ph[kk2][2], Ph[kk2][3], h0, h1);
                mma16816(oa[dnb][0], oa[dnb][1], oa[dnb][2], oa[dnb][3],
                         Pl[kk2][0], Pl[kk2][1], Pl[kk2][2], Pl[kk2][3], h0, h1);
                mma16816(oa[dnb + 1][0], oa[dnb + 1][1], oa[dnb + 1][2], oa[dnb + 1][3],
                         Ph[kk2][0], Ph[kk2][1], Ph[kk2][2], Ph[kk2][3], h2, h3);
                mma16816(oa[dnb + 1][0], oa[dnb + 1][1], oa[dnb + 1][2], oa[dnb + 1][3],
                         Pl[kk2][0], Pl[kk2][1], Pl[kk2][2], Pl[kk2][3], h2, h3);
            }
        }
    }

    float inv0 = 1.0f / l0, inv1 = 1.0f / l1;
    int r0 = i0 + warp * 16 + g;
    __half* ohb = oh + hoff;
    __half* olb = ol + hoff;
#pragma unroll
    for (int dnb = 0; dnb < 16; dnb++) {
        int col = dnb * 8 + 2 * q4;
        float a0 = oa[dnb][0] * inv0, a1 = oa[dnb][1] * inv0;
        float b0f = oa[dnb][2] * inv1, b1f = oa[dnb][3] * inv1;
        __half2 h0 = __floats2half2_rn(a0, a1);
        __half2 h1 = __floats2half2_rn(b0f, b1f);
        *(__half2*)&ohb[(size_t)r0 * DMODEL + col] = h0;
        *(__half2*)&ohb[(size_t)(r0 + 8) * DMODEL + col] = h1;
        __half2 lo0 = __floats2half2_rn(a0 - __half2float(__low2half(h0)),
                                        a1 - __half2float(__high2half(h0)));
        __half2 lo1 = __floats2half2_rn(b0f - __half2float(__low2half(h1)),
                                        b1f - __half2float(__high2half(h1)));
        *(__half2*)&olb[(size_t)r0 * DMODEL + col] = lo0;
        *(__half2*)&olb[(size_t)(r0 + 8) * DMODEL + col] = lo1;
    }
}

// ---------------------------------------------------------------------------
extern "C" void kernel_launch(void* const* d_in, const int* in_sizes, int n_in,
                              void* d_out, int out_size)
{
    const float* x  = (const float*)d_in[0];
    const float* Wq = (const float*)d_in[1];
    const float* bq = (const float*)d_in[2];
    const float* Wk = (const float*)d_in[3];
    const float* bk = (const float*)d_in[4];
    const float* Wv = (const float*)d_in[5];
    const float* bv = (const float*)d_in[6];
    const float* Wo = (const float*)d_in[7];
    const float* bo = (const float*)d_in[8];
    float* out = (float*)d_out;

    __half *xhi, *ahi, *alo, *qhh, *qll, *khh, *vhh;
    __half *wq, *wk, *wv, *wo;
    cudaGetSymbolAddress((void**)&xhi, g_xhi);
    cudaGetSymbolAddress((void**)&ahi, g_ahi);
    cudaGetSymbolAddress((void**)&alo, g_alo);
    cudaGetSymbolAddress((void**)&qhh, g_qh);
    cudaGetSymbolAddress((void**)&qll, g_ql);
    cudaGetSymbolAddress((void**)&khh, g_kh);
    cudaGetSymbolAddress((void**)&vhh, g_vh);
    cudaGetSymbolAddress((void**)&wq, g_wq);
    cudaGetSymbolAddress((void**)&wk, g_wk);
    cudaGetSymbolAddress((void**)&wv, g_wv);
    cudaGetSymbolAddress((void**)&wo, g_wo);

    cudaFuncSetAttribute(gemm_qkv, cudaFuncAttributeMaxDynamicSharedMemorySize, QKV_SMEM);
    cudaFuncSetAttribute(gemm_2p, cudaFuncAttributeMaxDynamicSharedMemorySize, OUT_SMEM);
    cudaFuncSetAttribute(flash_attn_mma, cudaFuncAttributeMaxDynamicSharedMemorySize, ATT_SMEM);

    // prep: convert x, transpose+convert weights
    int n4x = ROWS * DMODEL / 4;
    cvt_kernel<<<(n4x + 255) / 256, 256>>>((const float4*)x, xhi, n4x);
    dim3 tgrid(DMODEL / 32, DMODEL / 32, 4);
    transpose_cvt4<<<tgrid, 256>>>(Wq, Wk, Wv, Wo, wq, wk, wv, wo);

    // fused QKV projection (single pass) + rotary + split
    dim3 qkv_grid(3 * DMODEL / TN, ROWS / TM);   // (48, 32)
    gemm_qkv<<<qkv_grid, 256, QKV_SMEM>>>(xhi, wq, wk, wv,
                                          bq, bk, bv, qhh, qll, khh, vhh);

    // tensor-core flash attention
    dim3 attn_grid(NSEQ / 64, BATCH * HEADS);   // (32, 32)
    flash_attn_mma<<<attn_grid, 128, ATT_SMEM>>>(qhh, qll, khh, vhh, ahi, alo);

    // output projection (two pass)
    dim3 ggrid(DMODEL / TN, ROWS / TM);   // (16, 32)
    gemm_2p<<<ggrid, 256, OUT_SMEM>>>(ahi, alo, wo, bo, out);
}

// round 12
// speedup vs baseline: 1.7249x; 1.2187x over previous
#include <cuda_runtime.h>
#include <cuda_fp16.h>
#include <math.h>
#include <stdint.h>

#define BATCH 2
#define NSEQ  2048
#define DMODEL 2048
#define HEADS 16
#define DHEAD 128
#define ROWS (BATCH*NSEQ)   // 4096

// ---------------------------------------------------------------------------
// scratch (device globals: no allocation allowed)
// ---------------------------------------------------------------------------
__device__ __half g_xhi[ROWS*DMODEL];
__device__ __half g_ahi[ROWS*DMODEL];
__device__ __half g_qh[ROWS*DMODEL];
__device__ __half g_ql[ROWS*DMODEL];
__device__ __half g_kh[ROWS*DMODEL];
__device__ __half g_vh[ROWS*DMODEL];
__device__ __half g_wq[DMODEL*DMODEL];
__device__ __half g_wk[DMODEL*DMODEL];
__device__ __half g_wv[DMODEL*DMODEL];
__device__ __half g_wo[DMODEL*DMODEL];

// ---------------------------------------------------------------------------
// helpers
// ---------------------------------------------------------------------------
__device__ __forceinline__ uint32_t smem_u32(const void* p) {
    uint32_t a;
    asm("{ .reg .u64 t; cvta.to.shared.u64 t, %1; cvt.u32.u64 %0, t; }" : "=r"(a) : "l"(p));
    return a;
}

__device__ __forceinline__ void cp16(uint32_t dst, const void* src) {
    asm volatile("cp.async.cg.shared.global [%0], [%1], 16;" :: "r"(dst), "l"(src));
}
#define CP_COMMIT() asm volatile("cp.async.commit_group;" ::: "memory")
#define CP_WAIT(n)  asm volatile("cp.async.wait_group %0;" :: "n"(n) : "memory")

__device__ __forceinline__ void ldmx4(uint32_t addr, uint32_t& r0, uint32_t& r1,
                                      uint32_t& r2, uint32_t& r3) {
    asm volatile("ldmatrix.sync.aligned.m8n8.x4.shared.b16 {%0,%1,%2,%3}, [%4];"
                 : "=r"(r0), "=r"(r1), "=r"(r2), "=r"(r3) : "r"(addr));
}
__device__ __forceinline__ void ldmx4t(uint32_t addr, uint32_t& r0, uint32_t& r1,
                                       uint32_t& r2, uint32_t& r3) {
    asm volatile("ldmatrix.sync.aligned.m8n8.x4.trans.shared.b16 {%0,%1,%2,%3}, [%4];"
                 : "=r"(r0), "=r"(r1), "=r"(r2), "=r"(r3) : "r"(addr));
}

// fp16 inputs, fp32 accumulate
__device__ __forceinline__ void mma16816(float& c0, float& c1, float& c2, float& c3,
                                         uint32_t a0, uint32_t a1, uint32_t a2, uint32_t a3,
                                         uint32_t b0, uint32_t b1) {
    asm volatile(
        "mma.sync.aligned.m16n8k16.row.col.f32.f16.f16.f32 "
        "{%0,%1,%2,%3}, {%4,%5,%6,%7}, {%8,%9}, {%0,%1,%2,%3};"
        : "+f"(c0), "+f"(c1), "+f"(c2), "+f"(c3)
        : "r"(a0), "r"(a1), "r"(a2), "r"(a3), "r"(b0), "r"(b1));
}

// ---------------------------------------------------------------------------
// convert: fp32 -> fp16 (hi only)
// ---------------------------------------------------------------------------
__global__ __launch_bounds__(256)
void cvt_kernel(const float4* __restrict__ in, __half* __restrict__ hi, int n4)
{
    int i = blockIdx.x * 256 + threadIdx.x;
    if (i >= n4) return;
    float4 v = in[i];
    __half2* hp = (__half2*)(hi + 4 * (size_t)i);
    hp[0] = __floats2half2_rn(v.x, v.y);
    hp[1] = __floats2half2_rn(v.z, v.w);
}

// ---------------------------------------------------------------------------
// transpose + convert: W[K][N] fp32 -> Wt[N][K] fp16 (hi only), 4 weights
// ---------------------------------------------------------------------------
__global__ __launch_bounds__(256)
void transpose_cvt4(const float* __restrict__ W0, const float* __restrict__ W1,
                    const float* __restrict__ W2, const float* __restrict__ W3,
                    __half* __restrict__ t0, __half* __restrict__ t1,
                    __half* __restrict__ t2, __half* __restrict__ t3)
{
    int z = blockIdx.z;
    const float* W = (z == 0) ? W0 : (z == 1) ? W1 : (z == 2) ? W2 : W3;
    __half* th = (z == 0) ? t0 : (z == 1) ? t1 : (z == 2) ? t2 : t3;

    __shared__ float t[32][33];
    int n0 = blockIdx.x * 32, k0 = blockIdx.y * 32;
    int tx = threadIdx.x & 31, ty = threadIdx.x >> 5;
#pragma unroll
    for (int i = 0; i < 32; i += 8)
        t[ty + i][tx] = W[(size_t)(k0 + ty + i) * DMODEL + n0 + tx];
    __syncthreads();
#pragma unroll
    for (int i = 0; i < 32; i += 8)
        th[(size_t)(n0 + ty + i) * DMODEL + k0 + tx] = __float2half(t[tx][ty + i]);
}

// ---------------------------------------------------------------------------
// GEMM config: CTA 128x128, 256 threads, warp tile 64x32, KC=64, single-pass
// ---------------------------------------------------------------------------
#define GK DMODEL
#define TM 128
#define TN 128
#define KC 64
#define RSTRB 144u                     // bytes per smem row (128 data + 16 pad)
#define TILE_B (128u * RSTRB)          // 18432
#define STAGE1_B (2u * TILE_B)         // 36864 (Ah, Bh)
#define GEMM1_SMEM (2u * STAGE1_B)     // 73728

// single-pass mainloop shared by both GEMMs (needs: sb, tid, wid, lane, wm, wn,
// Ahi, Bhh, brow, bcol, acc). copy-before-wait double buffering.
#define GEMM1_BODY(ACC)                                                                 \
    auto copy_chunk = [&](int c, int stg) {                                             \
        int k0 = c * KC;                                                                \
        uint32_t base = sb + (uint32_t)stg * STAGE1_B;                                  \
        const __half* srcs[2] = { Ahi, Bhh };                                           \
        int rows0[2] = { brow, bcol };                                                  \
        _Pragma("unroll")                                                               \
        for (int t = 0; t < 2; t++) {                                                   \
            const __half* src = srcs[t] + (size_t)rows0[t] * GK + k0;                   \
            uint32_t tb = base + (uint32_t)t * TILE_B;                                  \
            _Pragma("unroll")                                                           \
            for (int i = 0; i < 4; i++) {                                               \
                int s = i * 256 + tid;                                                  \
                int r = s >> 3, seg = s & 7;                                            \
                cp16(tb + (uint32_t)r * RSTRB + (uint32_t)seg * 16u,                    \
                     src + (size_t)r * GK + seg * 8);                                   \
            }                                                                           \
        }                                                                               \
        CP_COMMIT();                                                                    \
    };                                                                                  \
    const int NCH = GK / KC;                                                            \
    copy_chunk(0, 0);                                                                   \
    const uint32_t lrow = (uint32_t)(lane & 15);                                        \
    const uint32_t lcol2 = (uint32_t)((lane >> 4) & 1) * 16u;                           \
    for (int c = 0; c < NCH; c++) {                                                     \
        int stg = c & 1;                                                                \
        if (c + 1 < NCH) {                                                              \
            copy_chunk(c + 1, stg ^ 1);                                                 \
            CP_WAIT(1);                                                                 \
        } else {                                                                        \
            CP_WAIT(0);                                                                 \
        }                                                                               \
        __syncthreads();                                                                \
        uint32_t base = sb + (uint32_t)stg * STAGE1_B;                                  \
        uint32_t ah_b = base;                                                           \
        uint32_t bh_b = base + TILE_B;                                                  \
        _Pragma("unroll")                                                               \
        for (int kk = 0; kk < 4; kk++) {                                                \
            uint32_t koff = (uint32_t)kk * 32u + lcol2;                                 \
            uint32_t Ah[4][4];                                                          \
            _Pragma("unroll")                                                           \
            for (int mi = 0; mi < 4; mi++) {                                            \
                uint32_t roff = ((uint32_t)(wm * 64 + mi * 16) + lrow) * RSTRB + koff;  \
                ldmx4(ah_b + roff, Ah[mi][0], Ah[mi][1], Ah[mi][2], Ah[mi][3]);         \
            }                                                                           \
            uint32_t Bh[4][2];                                                          \
            _Pragma("unroll")                                                           \
            for (int np = 0; np < 2; np++) {                                            \
                uint32_t roff = ((uint32_t)(wn * 32 + np * 16) + lrow) * RSTRB + koff;  \
                uint32_t r0, r1, r2, r3;                                                \
                ldmx4(bh_b + roff, r0, r1, r2, r3);                                     \
                Bh[np * 2][0] = r0; Bh[np * 2 + 1][0] = r1;                             \
                Bh[np * 2][1] = r2; Bh[np * 2 + 1][1] = r3;                             \
            }                                                                           \
            _Pragma("unroll")                                                           \
            for (int mi = 0; mi < 4; mi++)                                              \
                _Pragma("unroll")                                                       \
                for (int ni = 0; ni < 4; ni++)                                          \
                    mma16816(ACC[mi][ni][0], ACC[mi][ni][1], ACC[mi][ni][2], ACC[mi][ni][3], \
                             Ah[mi][0], Ah[mi][1], Ah[mi][2], Ah[mi][3],                \
                             Bh[ni][0], Bh[ni][1]);                                     \
        }                                                                               \
        __syncthreads();                                                                \
    }

// ---------------------------------------------------------------------------
// Fused QKV GEMM (single pass) + rotary + fp16 split epilogue. grid (48, 32).
// q -> hi+lo; k,v -> hi only.
// ---------------------------------------------------------------------------
__global__ __launch_bounds__(256, 2)
void gemm_qkv(const __half* __restrict__ xhi,
              const __half* __restrict__ wq, const __half* __restrict__ wk,
              const __half* __restrict__ wv,
              const float* __restrict__ bq, const float* __restrict__ bk,
              const float* __restrict__ bv,
              __half* __restrict__ qh, __half* __restrict__ ql,
              __half* __restrict__ kh, __half* __restrict__ vh)
{
    extern __shared__ __align__(128) char smem[];
    uint32_t sb = smem_u32(smem);
    const int tid  = threadIdx.x;
    const int wid  = tid >> 5;
    const int lane = tid & 31;
    const int brow = blockIdx.y * TM;
    const int mtx  = blockIdx.x >> 4;
    const int bcol = (blockIdx.x & 15) * TN;

    const __half* Ahi = xhi;
    const __half* Bhh = (mtx == 0) ? wq : (mtx == 1) ? wk : wv;
    const float* bias = (mtx == 0) ? bq : (mtx == 1) ? bk : bv;

    const int wm = wid & 1;
    const int wn = wid >> 1;

    float acc[4][4][4];
#pragma unroll
    for (int i = 0; i < 4; i++)
#pragma unroll
        for (int j = 0; j < 4; j++)
#pragma unroll
            for (int r = 0; r < 4; r++) acc[i][j][r] = 0.f;

    GEMM1_BODY(acc)

    // ------ fused epilogue: stage fp32 tile in smem, rotary+split, store ----
    float* ft = (float*)smem;    // [128][132] fp32 = 67584 B (< 73728)
    int g = lane >> 2, t4 = lane & 3;
#pragma unroll
    for (int mi = 0; mi < 4; mi++) {
        int r0 = wm * 64 + mi * 16 + g;
#pragma unroll
        for (int ni = 0; ni < 4; ni++) {
            int cl = wn * 32 + ni * 8 + 2 * t4;
            float2 b01 = *(const float2*)&bias[bcol + cl];
            *(float2*)&ft[r0 * 132 + cl] =
                make_float2(acc[mi][ni][0] + b01.x, acc[mi][ni][1] + b01.y);
            *(float2*)&ft[(r0 + 8) * 132 + cl] =
                make_float2(acc[mi][ni][2] + b01.x, acc[mi][ni][3] + b01.y);
        }
    }
    __syncthreads();

    const bool  do_rot = (mtx < 2);
    const float scale  = (mtx == 0) ? 0.08838834764831845f : 1.0f;
    int d  = tid & 63;
    int rb = tid >> 6;
    float inv_freq = __expf(-(float)d * (9.210340371976184f / 64.0f));

    for (int rr = rb; rr < 128; rr += 4) {
        int grow = brow + rr;
        float a = ft[rr * 132 + d];
        float b2 = ft[rr * 132 + d + 64];
        float oa, ob2;
        if (do_rot) {
            int n = grow & (NSEQ - 1);
            float s, c;
            sincosf((float)n * inv_freq, &s, &c);
            oa  = (a * c - b2 * s) * scale;
            ob2 = (b2 * c + a * s) * scale;
        } else {
            oa = a; ob2 = b2;
        }
        size_t base = (size_t)grow * DMODEL + bcol + d;
        if (mtx == 0) {
            __half h = __float2half(oa);
            qh[base] = h;
            ql[base] = __float2half(oa - __half2float(h));
            h = __float2half(ob2);
            qh[base + 64] = h;
            ql[base + 64] = __float2half(ob2 - __half2float(h));
        } else {
            __half* Oh = (mtx == 1) ? kh : vh;
            Oh[base]      = __float2half(oa);
            Oh[base + 64] = __float2half(ob2);
        }
    }
}

// ---------------------------------------------------------------------------
// Out projection GEMM (single pass), fp32 output + bias
// ---------------------------------------------------------------------------
__global__ __launch_bounds__(256, 2)
void gemm_1p(const __half* __restrict__ Ahi, const __half* __restrict__ Bhh,
             const float* __restrict__ bias, float* __restrict__ C)
{
    extern __shared__ __align__(128) char smem[];
    uint32_t sb = smem_u32(smem);
    const int tid  = threadIdx.x;
    const int wid  = tid >> 5;
    const int lane = tid & 31;
    const int brow = blockIdx.y * TM;
    const int bcol = blockIdx.x * TN;

    const int wm = wid & 1;
    const int wn = wid >> 1;

    float acc[4][4][4];
#pragma unroll
    for (int i = 0; i < 4; i++)
#pragma unroll
        for (int j = 0; j < 4; j++)
#pragma unroll
            for (int r = 0; r < 4; r++) acc[i][j][r] = 0.f;

    GEMM1_BODY(acc)

    int g = lane >> 2, t4 = lane & 3;
#pragma unroll
    for (int mi = 0; mi < 4; mi++) {
        int r0 = brow + wm * 64 + mi * 16 + g;
#pragma unroll
        for (int ni = 0; ni < 4; ni++) {
            int col = bcol + wn * 32 + ni * 8 + 2 * t4;
            float2 b01 = *(const float2*)&bias[col];
            float2 o0, o1;
            o0.x = acc[mi][ni][0] + b01.x;
            o0.y = acc[mi][ni][1] + b01.y;
            o1.x = acc[mi][ni][2] + b01.x;
            o1.y = acc[mi][ni][3] + b01.y;
            *(float2*)&C[(size_t)r0 * DMODEL + col]       = o0;
            *(float2*)&C[(size_t)(r0 + 8) * DMODEL + col] = o1;
        }
    }
}

// ---------------------------------------------------------------------------
// Flash attention (causal): S=(Qh+Ql)Kh (2-pass), O=Ph*Vh (single pass).
// BR=BC=64, 128 threads, Q in regs, 4 rotating K/V buffers.
// ---------------------------------------------------------------------------
#define ABUF_B 17408u
#define ATT_SMEM (4u * ABUF_B)        // 69632

__global__ __launch_bounds__(128)
void flash_attn_mma(const __half* __restrict__ qh, const __half* __restrict__ ql,
                    const __half* __restrict__ kh, const __half* __restrict__ vh,
                    __half* __restrict__ oh)
{
    extern __shared__ __align__(128) char smem[];
    uint32_t sb = smem_u32(smem);

    const int tid  = threadIdx.x;
    const int warp = tid >> 5;
    const int lane = tid & 31;
    const int g    = lane >> 2;
    const int q4   = lane & 3;

    const int it = gridDim.x - 1 - blockIdx.x;   // heavy tiles first
    const int bh = blockIdx.y;
    const int b = bh >> 4, h = bh & 15;
    const int i0 = it * 64;

    const size_t hoff = (size_t)b * NSEQ * DMODEL + h * DHEAD;
    const __half* qhb = qh + hoff;
    const __half* qlb = ql + hoff;
    const __half* khb = kh + hoff;
    const __half* vhb = vh + hoff;

    auto copyTile = [&](const __half* src, int row0, uint32_t buf) {
#pragma unroll
        for (int i = 0; i < 8; i++) {
            int s = i * 128 + tid;
            int r = s >> 4, seg = s & 15;
            cp16(buf + (uint32_t)r * 272u + (uint32_t)seg * 16u,
                 src + (size_t)(row0 + r) * DMODEL + seg * 8);
        }
    };

    uint32_t K0 = sb, K1 = sb + ABUF_B, V0 = sb + 2u * ABUF_B, V1 = sb + 3u * ABUF_B;

    copyTile(qhb, i0, K1);
    copyTile(qlb, i0, V1);
    CP_COMMIT();
    copyTile(khb, 0, K0);
    copyTile(vhb, 0, V0);
    CP_COMMIT();

    CP_WAIT(1);
    __syncthreads();

    const uint32_t lrow = (uint32_t)(lane & 15);
    const uint32_t lseg16 = (uint32_t)(lane >> 4) * 16u;
    uint32_t Qh4[8][4], Ql4[8][4];
#pragma unroll
    for (int kk = 0; kk < 8; kk++) {
        uint32_t qoff = ((uint32_t)(warp * 16) + lrow) * 272u + lseg16 + (uint32_t)kk * 32u;
        ldmx4(K1 + qoff, Qh4[kk][0], Qh4[kk][1], Qh4[kk][2], Qh4[kk][3]);
        ldmx4(V1 + qoff, Ql4[kk][0], Ql4[kk][1], Ql4[kk][2], Ql4[kk][3]);
    }

    float m0 = -1e30f, m1 = -1e30f, l0 = 0.f, l1 = 0.f;
    float oa[16][4];
#pragma unroll
    for (int d = 0; d < 16; d++)
#pragma unroll
        for (int r = 0; r < 4; r++) oa[d][r] = 0.f;

    const int NJT = it + 1;

    for (int jt = 0; jt < NJT; jt++) {
        int stg = jt & 1;
        uint32_t kb = stg ? K1 : K0;
        uint32_t vb = stg ? V1 : V0;

        CP_WAIT(0);
        __syncthreads();
        if (jt + 1 < NJT) {
            copyTile(khb, (jt + 1) * 64, stg ? K0 : K1);
            copyTile(vhb, (jt + 1) * 64, stg ? V0 : V1);
            CP_COMMIT();
        }

        // ===== S = (Qh+Ql) @ Kh^T =====
        float s[8][4];
#pragma unroll
        for (int nb = 0; nb < 8; nb++)
#pragma unroll
            for (int r = 0; r < 4; r++) s[nb][r] = 0.f;

#pragma unroll
        for (int kk = 0; kk < 8; kk++) {
#pragma unroll
            for (int np = 0; np < 4; np++) {
                uint32_t koff = ((uint32_t)(np * 16) + lrow) * 272u + lseg16 + (uint32_t)kk * 32u;
                uint32_t h0, h1, h2, h3;
                ldmx4(kb + koff, h0, h1, h2, h3);
                int nb = np * 2;
                mma16816(s[nb][0], s[nb][1], s[nb][2], s[nb][3],
                         Qh4[kk][0], Qh4[kk][1], Qh4[kk][2], Qh4[kk][3], h0, h2);
                mma16816(s[nb][0], s[nb][1], s[nb][2], s[nb][3],
                         Ql4[kk][0], Ql4[kk][1], Ql4[kk][2], Ql4[kk][3], h0, h2);
                mma16816(s[nb + 1][0], s[nb + 1][1], s[nb + 1][2], s[nb + 1][3],
                         Qh4[kk][0], Qh4[kk][1], Qh4[kk][2], Qh4[kk][3], h1, h3);
                mma16816(s[nb + 1][0], s[nb + 1][1], s[nb + 1][2], s[nb + 1][3],
                         Ql4[kk][0], Ql4[kk][1], Ql4[kk][2], Ql4[kk][3], h1, h3);
            }
        }

        // causal mask on diagonal tile
        if (jt == it) {
            int r0 = warp * 16 + g;
            int r1 = r0 + 8;
#pragma unroll
            for (int nb = 0; nb < 8; nb++) {
                int c0 = nb * 8 + 2 * q4;
                if (c0 > r0)     s[nb][0] = -1e30f;
                if (c0 + 1 > r0) s[nb][1] = -1e30f;
                if (c0 > r1)     s[nb][2] = -1e30f;
                if (c0 + 1 > r1) s[nb][3] = -1e30f;
            }
        }

        // online softmax
        float mx0 = -1e30f, mx1 = -1e30f;
#pragma unroll
        for (int nb = 0; nb < 8; nb++) {
            mx0 = fmaxf(mx0, fmaxf(s[nb][0], s[nb][1]));
            mx1 = fmaxf(mx1, fmaxf(s[nb][2], s[nb][3]));
        }
        mx0 = fmaxf(mx0, __shfl_xor_sync(0xffffffffu, mx0, 1));
        mx0 = fmaxf(mx0, __shfl_xor_sync(0xffffffffu, mx0, 2));
        mx1 = fmaxf(mx1, __shfl_xor_sync(0xffffffffu, mx1, 1));
        mx1 = fmaxf(mx1, __shfl_xor_sync(0xffffffffu, mx1, 2));

        float m0n = fmaxf(m0, mx0), m1n = fmaxf(m1, mx1);
        float f0 = __expf(m0 - m0n), f1 = __expf(m1 - m1n);

        float sum0 = 0.f, sum1 = 0.f;
#pragma unroll
        for (int nb = 0; nb < 8; nb++) {
            s[nb][0] = __expf(s[nb][0] - m0n);
            s[nb][1] = __expf(s[nb][1] - m0n);
            s[nb][2] = __expf(s[nb][2] - m1n);
            s[nb][3] = __expf(s[nb][3] - m1n);
            sum0 += s[nb][0] + s[nb][1];
            sum1 += s[nb][2] + s[nb][3];
        }
        sum0 += __shfl_xor_sync(0xffffffffu, sum0, 1);
        sum0 += __shfl_xor_sync(0xffffffffu, sum0, 2);
        sum1 += __shfl_xor_sync(0xffffffffu, sum1, 1);
        sum1 += __shfl_xor_sync(0xffffffffu, sum1, 2);

        m0 = m0n; m1 = m1n;
        l0 = l0 * f0 + sum0;
        l1 = l1 * f1 + sum1;

#pragma unroll
        for (int d = 0; d < 16; d++) {
            oa[d][0] *= f0; oa[d][1] *= f0;
            oa[d][2] *= f1; oa[d][3] *= f1;
        }

        // P -> fp16 A-frags (hi only)
        uint32_t Ph[4][4];
#pragma unroll
        for (int kk2 = 0; kk2 < 4; kk2++) {
            int nb = 2 * kk2;
#pragma unroll
            for (int half = 0; half < 2; half++) {
                int src = nb + half;
                __half2 hA = __floats2half2_rn(s[src][0], s[src][1]);
                __half2 hB = __floats2half2_rn(s[src][2], s[src][3]);
                Ph[kk2][half * 2 + 0] = *(uint32_t*)&hA;
                Ph[kk2][half * 2 + 1] = *(uint32_t*)&hB;
            }
        }

        // ===== O += Ph @ Vh (single pass) =====
#pragma unroll
        for (int kk2 = 0; kk2 < 4; kk2++) {
#pragma unroll
            for (int dp = 0; dp < 8; dp++) {
                uint32_t voff = ((uint32_t)(kk2 * 16) + lrow) * 272u
                              + (uint32_t)dp * 32u + lseg16;
                uint32_t h0, h1, h2, h3;
                ldmx4t(vb + voff, h0, h1, h2, h3);
                int dnb = dp * 2;
                mma16816(oa[dnb][0], oa[dnb][1], oa[dnb][2], oa[dnb][3],
                         Ph[kk2][0], Ph[kk2][1], Ph[kk2][2], Ph[kk2][3], h0, h1);
                mma16816(oa[dnb + 1][0], oa[dnb + 1][1], oa[dnb + 1][2], oa[dnb + 1][3],
                         Ph[kk2][0], Ph[kk2][1], Ph[kk2][2], Ph[kk2][3], h2, h3);
            }
        }
    }

    // epilogue: normalize, store fp16 (hi only)
    float inv0 = 1.0f / l0, inv1 = 1.0f / l1;
    int r0 = i0 + warp * 16 + g;
    __half* ohb = oh + hoff;
#pragma unroll
    for (int dnb = 0; dnb < 16; dnb++) {
        int col = dnb * 8 + 2 * q4;
        __half2 h0 = __floats2half2_rn(oa[dnb][0] * inv0, oa[dnb][1] * inv0);
        __half2 h1 = __floats2half2_rn(oa[dnb][2] * inv1, oa[dnb][3] * inv1);
        *(__half2*)&ohb[(size_t)r0 * DMODEL + col] = h0;
        *(__half2*)&ohb[(size_t)(r0 + 8) * DMODEL + col] = h1;
    }
}

// ---------------------------------------------------------------------------
extern "C" void kernel_launch(void* const* d_in, const int* in_sizes, int n_in,
                              void* d_out, int out_size)
{
    const float* x  = (const float*)d_in[0];
    const float* Wq = (const float*)d_in[1];
    const float* bq = (const float*)d_in[2];
    const float* Wk = (const float*)d_in[3];
    const float* bk = (const float*)d_in[4];
    const float* Wv = (const float*)d_in[5];
    const float* bv = (const float*)d_in[6];
    const float* Wo = (const float*)d_in[7];
    const float* bo = (const float*)d_in[8];
    float* out = (float*)d_out;

    __half *xhi, *ahi, *qhh, *qll, *khh, *vhh;
    __half *wq, *wk, *wv, *wo;
    cudaGetSymbolAddress((void**)&xhi, g_xhi);
    cudaGetSymbolAddress((void**)&ahi, g_ahi);
    cudaGetSymbolAddress((void**)&qhh, g_qh);
    cudaGetSymbolAddress((void**)&qll, g_ql);
    cudaGetSymbolAddress((void**)&khh, g_kh);
    cudaGetSymbolAddress((void**)&vhh, g_vh);
    cudaGetSymbolAddress((void**)&wq, g_wq);
    cudaGetSymbolAddress((void**)&wk, g_wk);
    cudaGetSymbolAddress((void**)&wv, g_wv);
    cudaGetSymbolAddress((void**)&wo, g_wo);

    cudaFuncSetAttribute(gemm_qkv, cudaFuncAttributeMaxDynamicSharedMemorySize, GEMM1_SMEM);
    cudaFuncSetAttribute(gemm_1p, cudaFuncAttributeMaxDynamicSharedMemorySize, GEMM1_SMEM);
    cudaFuncSetAttribute(flash_attn_mma, cudaFuncAttributeMaxDynamicSharedMemorySize, ATT_SMEM);

    // prep: convert x, transpose+convert weights
    int n4x = ROWS * DMODEL / 4;
    cvt_kernel<<<(n4x + 255) / 256, 256>>>((const float4*)x, xhi, n4x);
    dim3 tgrid(DMODEL / 32, DMODEL / 32, 4);
    transpose_cvt4<<<tgrid, 256>>>(Wq, Wk, Wv, Wo, wq, wk, wv, wo);

    // fused QKV projection (single pass) + rotary + split
    dim3 qkv_grid(3 * DMODEL / TN, ROWS / TM);   // (48, 32)
    gemm_qkv<<<qkv_grid, 256, GEMM1_SMEM>>>(xhi, wq, wk, wv,
                                            bq, bk, bv, qhh, qll, khh, vhh);

    // tensor-core flash attention (PV single pass)
    dim3 attn_grid(NSEQ / 64, BATCH * HEADS);   // (32, 32)
    flash_attn_mma<<<attn_grid, 128, ATT_SMEM>>>(qhh, qll, khh, vhh, ahi);

    // output projection (single pass)
    dim3 ggrid(DMODEL / TN, ROWS / TM);   // (16, 32)
    gemm_1p<<<ggrid, 256, GEMM1_SMEM>>>(ahi, wo, bo, out);
}

// round 13
// speedup vs baseline: 1.8049x; 1.0464x over previous
#include <cuda_runtime.h>
#include <cuda_fp16.h>
#include <math.h>
#include <stdint.h>

#define BATCH 2
#define NSEQ  2048
#define DMODEL 2048
#define HEADS 16
#define DHEAD 128
#define ROWS (BATCH*NSEQ)   // 4096

// ---------------------------------------------------------------------------
// scratch (device globals: no allocation allowed)
// ---------------------------------------------------------------------------
__device__ __half g_xhi[ROWS*DMODEL];
__device__ __half g_ahi[ROWS*DMODEL];
__device__ __half g_qh[ROWS*DMODEL];
__device__ __half g_kh[ROWS*DMODEL];
__device__ __half g_vh[ROWS*DMODEL];
__device__ __half g_wq[DMODEL*DMODEL];
__device__ __half g_wk[DMODEL*DMODEL];
__device__ __half g_wv[DMODEL*DMODEL];
__device__ __half g_wo[DMODEL*DMODEL];

// ---------------------------------------------------------------------------
// helpers
// ---------------------------------------------------------------------------
__device__ __forceinline__ uint32_t smem_u32(const void* p) {
    uint32_t a;
    asm("{ .reg .u64 t; cvta.to.shared.u64 t, %1; cvt.u32.u64 %0, t; }" : "=r"(a) : "l"(p));
    return a;
}

__device__ __forceinline__ void cp16(uint32_t dst, const void* src) {
    asm volatile("cp.async.cg.shared.global [%0], [%1], 16;" :: "r"(dst), "l"(src));
}
#define CP_COMMIT() asm volatile("cp.async.commit_group;" ::: "memory")
#define CP_WAIT(n)  asm volatile("cp.async.wait_group %0;" :: "n"(n) : "memory")

__device__ __forceinline__ void ldmx4(uint32_t addr, uint32_t& r0, uint32_t& r1,
                                      uint32_t& r2, uint32_t& r3) {
    asm volatile("ldmatrix.sync.aligned.m8n8.x4.shared.b16 {%0,%1,%2,%3}, [%4];"
                 : "=r"(r0), "=r"(r1), "=r"(r2), "=r"(r3) : "r"(addr));
}
__device__ __forceinline__ void ldmx4t(uint32_t addr, uint32_t& r0, uint32_t& r1,
                                       uint32_t& r2, uint32_t& r3) {
    asm volatile("ldmatrix.sync.aligned.m8n8.x4.trans.shared.b16 {%0,%1,%2,%3}, [%4];"
                 : "=r"(r0), "=r"(r1), "=r"(r2), "=r"(r3) : "r"(addr));
}

// fp16 inputs, fp32 accumulate
__device__ __forceinline__ void mma16816(float& c0, float& c1, float& c2, float& c3,
                                         uint32_t a0, uint32_t a1, uint32_t a2, uint32_t a3,
                                         uint32_t b0, uint32_t b1) {
    asm volatile(
        "mma.sync.aligned.m16n8k16.row.col.f32.f16.f16.f32 "
        "{%0,%1,%2,%3}, {%4,%5,%6,%7}, {%8,%9}, {%0,%1,%2,%3};"
        : "+f"(c0), "+f"(c1), "+f"(c2), "+f"(c3)
        : "r"(a0), "r"(a1), "r"(a2), "r"(a3), "r"(b0), "r"(b1));
}

// ---------------------------------------------------------------------------
// convert: fp32 -> fp16 (hi only)
// ---------------------------------------------------------------------------
__global__ __launch_bounds__(256)
void cvt_kernel(const float4* __restrict__ in, __half* __restrict__ hi, int n4)
{
    int i = blockIdx.x * 256 + threadIdx.x;
    if (i >= n4) return;
    float4 v = in[i];
    __half2* hp = (__half2*)(hi + 4 * (size_t)i);
    hp[0] = __floats2half2_rn(v.x, v.y);
    hp[1] = __floats2half2_rn(v.z, v.w);
}

// ---------------------------------------------------------------------------
// transpose + convert: W[K][N] fp32 -> Wt[N][K] fp16 (hi only), 4 weights
// ---------------------------------------------------------------------------
__global__ __launch_bounds__(256)
void transpose_cvt4(const float* __restrict__ W0, const float* __restrict__ W1,
                    const float* __restrict__ W2, const float* __restrict__ W3,
                    __half* __restrict__ t0, __half* __restrict__ t1,
                    __half* __restrict__ t2, __half* __restrict__ t3)
{
    int z = blockIdx.z;
    const float* W = (z == 0) ? W0 : (z == 1) ? W1 : (z == 2) ? W2 : W3;
    __half* th = (z == 0) ? t0 : (z == 1) ? t1 : (z == 2) ? t2 : t3;

    __shared__ float t[32][33];
    int n0 = blockIdx.x * 32, k0 = blockIdx.y * 32;
    int tx = threadIdx.x & 31, ty = threadIdx.x >> 5;
#pragma unroll
    for (int i = 0; i < 32; i += 8)
        t[ty + i][tx] = W[(size_t)(k0 + ty + i) * DMODEL + n0 + tx];
    __syncthreads();
#pragma unroll
    for (int i = 0; i < 32; i += 8)
        th[(size_t)(n0 + ty + i) * DMODEL + k0 + tx] = __float2half(t[tx][ty + i]);
}

// ---------------------------------------------------------------------------
// GEMM config: CTA 128x128, 256 threads, warp tile 64x32, KC=64, single-pass
// ---------------------------------------------------------------------------
#define GK DMODEL
#define TM 128
#define TN 128
#define KC 64
#define RSTRB 144u                     // bytes per smem row (128 data + 16 pad)
#define TILE_B (128u * RSTRB)          // 18432
#define STAGE1_B (2u * TILE_B)         // 36864 (Ah, Bh)
#define GEMM1_SMEM (2u * STAGE1_B)     // 73728

// single-pass mainloop shared by both GEMMs (needs: sb, tid, wid, lane, wm, wn,
// Ahi, Bhh, brow, bcol, acc). copy-before-wait double buffering.
#define GEMM1_BODY(ACC)                                                                 \
    auto copy_chunk = [&](int c, int stg) {                                             \
        int k0 = c * KC;                                                                \
        uint32_t base = sb + (uint32_t)stg * STAGE1_B;                                  \
        const __half* srcs[2] = { Ahi, Bhh };                                           \
        int rows0[2] = { brow, bcol };                                                  \
        _Pragma("unroll")                                                               \
        for (int t = 0; t < 2; t++) {                                                   \
            const __half* src = srcs[t] + (size_t)rows0[t] * GK + k0;                   \
            uint32_t tb = base + (uint32_t)t * TILE_B;                                  \
            _Pragma("unroll")                                                           \
            for (int i = 0; i < 4; i++) {                                               \
                int s = i * 256 + tid;                                                  \
                int r = s >> 3, seg = s & 7;                                            \
                cp16(tb + (uint32_t)r * RSTRB + (uint32_t)seg * 16u,                    \
                     src + (size_t)r * GK + seg * 8);                                   \
            }                                                                           \
        }                                                                               \
        CP_COMMIT();                                                                    \
    };                                                                                  \
    const int NCH = GK / KC;                                                            \
    copy_chunk(0, 0);                                                                   \
    const uint32_t lrow = (uint32_t)(lane & 15);                                        \
    const uint32_t lcol2 = (uint32_t)((lane >> 4) & 1) * 16u;                           \
    for (int c = 0; c < NCH; c++) {                                                     \
        int stg = c & 1;                                                                \
        if (c + 1 < NCH) {                                                              \
            copy_chunk(c + 1, stg ^ 1);                                                 \
            CP_WAIT(1);                                                                 \
        } else {                                                                        \
            CP_WAIT(0);                                                                 \
        }                                                                               \
        __syncthreads();                                                                \
        uint32_t base = sb + (uint32_t)stg * STAGE1_B;                                  \
        uint32_t ah_b = base;                                                           \
        uint32_t bh_b = base + TILE_B;                                                  \
        _Pragma("unroll")                                                               \
        for (int kk = 0; kk < 4; kk++) {                                                \
            uint32_t koff = (uint32_t)kk * 32u + lcol2;                                 \
            uint32_t Ah[4][4];                                                          \
            _Pragma("unroll")                                                           \
            for (int mi = 0; mi < 4; mi++) {                                            \
                uint32_t roff = ((uint32_t)(wm * 64 + mi * 16) + lrow) * RSTRB + koff;  \
                ldmx4(ah_b + roff, Ah[mi][0], Ah[mi][1], Ah[mi][2], Ah[mi][3]);         \
            }                                                                           \
            uint32_t Bh[4][2];                                                          \
            _Pragma("unroll")                                                           \
            for (int np = 0; np < 2; np++) {                                            \
                uint32_t roff = ((uint32_t)(wn * 32 + np * 16) + lrow) * RSTRB + koff;  \
                uint32_t r0, r1, r2, r3;                                                \
                ldmx4(bh_b + roff, r0, r1, r2, r3);                                     \
                Bh[np * 2][0] = r0; Bh[np * 2 + 1][0] = r1;                             \
                Bh[np * 2][1] = r2; Bh[np * 2 + 1][1] = r3;                             \
            }                                                                           \
            _Pragma("unroll")                                                           \
            for (int mi = 0; mi < 4; mi++)                                              \
                _Pragma("unroll")                                                       \
                for (int ni = 0; ni < 4; ni++)                                          \
                    mma16816(ACC[mi][ni][0], ACC[mi][ni][1], ACC[mi][ni][2], ACC[mi][ni][3], \
                             Ah[mi][0], Ah[mi][1], Ah[mi][2], Ah[mi][3],                \
                             Bh[ni][0], Bh[ni][1]);                                     \
        }                                                                               \
        __syncthreads();                                                                \
    }

// ---------------------------------------------------------------------------
// Fused QKV GEMM (single pass) + rotary + fp16 epilogue. grid (48, 32).
// All outputs stored hi-only.
// ---------------------------------------------------------------------------
__global__ __launch_bounds__(256, 2)
void gemm_qkv(const __half* __restrict__ xhi,
              const __half* __restrict__ wq, const __half* __restrict__ wk,
              const __half* __restrict__ wv,
              const float* __restrict__ bq, const float* __restrict__ bk,
              const float* __restrict__ bv,
              __half* __restrict__ qh, __half* __restrict__ kh, __half* __restrict__ vh)
{
    extern __shared__ __align__(128) char smem[];
    uint32_t sb = smem_u32(smem);
    const int tid  = threadIdx.x;
    const int wid  = tid >> 5;
    const int lane = tid & 31;
    const int brow = blockIdx.y * TM;
    const int mtx  = blockIdx.x >> 4;
    const int bcol = (blockIdx.x & 15) * TN;

    const __half* Ahi = xhi;
    const __half* Bhh = (mtx == 0) ? wq : (mtx == 1) ? wk : wv;
    const float* bias = (mtx == 0) ? bq : (mtx == 1) ? bk : bv;
    __half* Oh        = (mtx == 0) ? qh : (mtx == 1) ? kh : vh;

    const int wm = wid & 1;
    const int wn = wid >> 1;

    float acc[4][4][4];
#pragma unroll
    for (int i = 0; i < 4; i++)
#pragma unroll
        for (int j = 0; j < 4; j++)
#pragma unroll
            for (int r = 0; r < 4; r++) acc[i][j][r] = 0.f;

    GEMM1_BODY(acc)

    // ------ fused epilogue: stage fp32 tile in smem, rotary, store hi ----
    float* ft = (float*)smem;    // [128][132] fp32 = 67584 B (< 73728)
    int g = lane >> 2, t4 = lane & 3;
#pragma unroll
    for (int mi = 0; mi < 4; mi++) {
        int r0 = wm * 64 + mi * 16 + g;
#pragma unroll
        for (int ni = 0; ni < 4; ni++) {
            int cl = wn * 32 + ni * 8 + 2 * t4;
            float2 b01 = *(const float2*)&bias[bcol + cl];
            *(float2*)&ft[r0 * 132 + cl] =
                make_float2(acc[mi][ni][0] + b01.x, acc[mi][ni][1] + b01.y);
            *(float2*)&ft[(r0 + 8) * 132 + cl] =
                make_float2(acc[mi][ni][2] + b01.x, acc[mi][ni][3] + b01.y);
        }
    }
    __syncthreads();

    const bool  do_rot = (mtx < 2);
    const float scale  = (mtx == 0) ? 0.08838834764831845f : 1.0f;
    int d  = tid & 63;
    int rb = tid >> 6;
    float inv_freq = __expf(-(float)d * (9.210340371976184f / 64.0f));

    for (int rr = rb; rr < 128; rr += 4) {
        int grow = brow + rr;
        float a = ft[rr * 132 + d];
        float b2 = ft[rr * 132 + d + 64];
        float oa, ob2;
        if (do_rot) {
            int n = grow & (NSEQ - 1);
            float s, c;
            sincosf((float)n * inv_freq, &s, &c);
            oa  = (a * c - b2 * s) * scale;
            ob2 = (b2 * c + a * s) * scale;
        } else {
            oa = a; ob2 = b2;
        }
        size_t base = (size_t)grow * DMODEL + bcol + d;
        Oh[base]      = __float2half(oa);
        Oh[base + 64] = __float2half(ob2);
    }
}

// ---------------------------------------------------------------------------
// Out projection GEMM (single pass), fp32 output + bias
// ---------------------------------------------------------------------------
__global__ __launch_bounds__(256, 2)
void gemm_1p(const __half* __restrict__ Ahi, const __half* __restrict__ Bhh,
             const float* __restrict__ bias, float* __restrict__ C)
{
    extern __shared__ __align__(128) char smem[];
    uint32_t sb = smem_u32(smem);
    const int tid  = threadIdx.x;
    const int wid  = tid >> 5;
    const int lane = tid & 31;
    const int brow = blockIdx.y * TM;
    const int bcol = blockIdx.x * TN;

    const int wm = wid & 1;
    const int wn = wid >> 1;

    float acc[4][4][4];
#pragma unroll
    for (int i = 0; i < 4; i++)
#pragma unroll
        for (int j = 0; j < 4; j++)
#pragma unroll
            for (int r = 0; r < 4; r++) acc[i][j][r] = 0.f;

    GEMM1_BODY(acc)

    int g = lane >> 2, t4 = lane & 3;
#pragma unroll
    for (int mi = 0; mi < 4; mi++) {
        int r0 = brow + wm * 64 + mi * 16 + g;
#pragma unroll
        for (int ni = 0; ni < 4; ni++) {
            int col = bcol + wn * 32 + ni * 8 + 2 * t4;
            float2 b01 = *(const float2*)&bias[col];
            float2 o0, o1;
            o0.x = acc[mi][ni][0] + b01.x;
            o0.y = acc[mi][ni][1] + b01.y;
            o1.x = acc[mi][ni][2] + b01.x;
            o1.y = acc[mi][ni][3] + b01.y;
            *(float2*)&C[(size_t)r0 * DMODEL + col]       = o0;
            *(float2*)&C[(size_t)(r0 + 8) * DMODEL + col] = o1;
        }
    }
}

// ---------------------------------------------------------------------------
// Flash attention (causal), fully single-pass fp16: S=Qh*Kh, O=Ph*Vh.
// BR=BC=64, 128 threads, Q in regs, 4 rotating K/V buffers.
// ---------------------------------------------------------------------------
#define ABUF_B 17408u
#define ATT_SMEM (4u * ABUF_B)        // 69632

__global__ __launch_bounds__(128)
void flash_attn_mma(const __half* __restrict__ qh, const __half* __restrict__ kh,
                    const __half* __restrict__ vh, __half* __restrict__ oh)
{
    extern __shared__ __align__(128) char smem[];
    uint32_t sb = smem_u32(smem);

    const int tid  = threadIdx.x;
    const int warp = tid >> 5;
    const int lane = tid & 31;
    const int g    = lane >> 2;
    const int q4   = lane & 3;

    const int it = gridDim.x - 1 - blockIdx.x;   // heavy tiles first
    const int bh = blockIdx.y;
    const int b = bh >> 4, h = bh & 15;
    const int i0 = it * 64;

    const size_t hoff = (size_t)b * NSEQ * DMODEL + h * DHEAD;
    const __half* qhb = qh + hoff;
    const __half* khb = kh + hoff;
    const __half* vhb = vh + hoff;

    auto copyTile = [&](const __half* src, int row0, uint32_t buf) {
#pragma unroll
        for (int i = 0; i < 8; i++) {
            int s = i * 128 + tid;
            int r = s >> 4, seg = s & 15;
            cp16(buf + (uint32_t)r * 272u + (uint32_t)seg * 16u,
                 src + (size_t)(row0 + r) * DMODEL + seg * 8);
        }
    };

    uint32_t K0 = sb, K1 = sb + ABUF_B, V0 = sb + 2u * ABUF_B, V1 = sb + 3u * ABUF_B;

    // stage Q in K1 (freed before jt=1 needs it), then KV(0)
    copyTile(qhb, i0, K1);
    CP_COMMIT();
    copyTile(khb, 0, K0);
    copyTile(vhb, 0, V0);
    CP_COMMIT();

    CP_WAIT(1);                 // Q done
    __syncthreads();

    const uint32_t lrow = (uint32_t)(lane & 15);
    const uint32_t lseg16 = (uint32_t)(lane >> 4) * 16u;
    uint32_t Qh4[8][4];
#pragma unroll
    for (int kk = 0; kk < 8; kk++) {
        uint32_t qoff = ((uint32_t)(warp * 16) + lrow) * 272u + lseg16 + (uint32_t)kk * 32u;
        ldmx4(K1 + qoff, Qh4[kk][0], Qh4[kk][1], Qh4[kk][2], Qh4[kk][3]);
    }

    float m0 = -1e30f, m1 = -1e30f, l0 = 0.f, l1 = 0.f;
    float oa[16][4];
#pragma unroll
    for (int d = 0; d < 16; d++)
#pragma unroll
        for (int r = 0; r < 4; r++) oa[d][r] = 0.f;

    const int NJT = it + 1;

    for (int jt = 0; jt < NJT; jt++) {
        int stg = jt & 1;
        uint32_t kb = stg ? K1 : K0;
        uint32_t vb = stg ? V1 : V0;

        CP_WAIT(0);
        __syncthreads();        // all warps done with previous buffers / Q frags
        if (jt + 1 < NJT) {
            copyTile(khb, (jt + 1) * 64, stg ? K0 : K1);
            copyTile(vhb, (jt + 1) * 64, stg ? V0 : V1);
            CP_COMMIT();
        }

        // ===== S = Qh @ Kh^T (single pass) =====
        float s[8][4];
#pragma unroll
        for (int nb = 0; nb < 8; nb++)
#pragma unroll
            for (int r = 0; r < 4; r++) s[nb][r] = 0.f;

#pragma unroll
        for (int kk = 0; kk < 8; kk++) {
#pragma unroll
            for (int np = 0; np < 4; np++) {
                uint32_t koff = ((uint32_t)(np * 16) + lrow) * 272u + lseg16 + (uint32_t)kk * 32u;
                uint32_t h0, h1, h2, h3;
                ldmx4(kb + koff, h0, h1, h2, h3);
                int nb = np * 2;
                mma16816(s[nb][0], s[nb][1], s[nb][2], s[nb][3],
                         Qh4[kk][0], Qh4[kk][1], Qh4[kk][2], Qh4[kk][3], h0, h2);
                mma16816(s[nb + 1][0], s[nb + 1][1], s[nb + 1][2], s[nb + 1][3],
                         Qh4[kk][0], Qh4[kk][1], Qh4[kk][2], Qh4[kk][3], h1, h3);
            }
        }

        // causal mask on diagonal tile
        if (jt == it) {
            int r0 = warp * 16 + g;
            int r1 = r0 + 8;
#pragma unroll
            for (int nb = 0; nb < 8; nb++) {
                int c0 = nb * 8 + 2 * q4;
                if (c0 > r0)     s[nb][0] = -1e30f;
                if (c0 + 1 > r0) s[nb][1] = -1e30f;
                if (c0 > r1)     s[nb][2] = -1e30f;
                if (c0 + 1 > r1) s[nb][3] = -1e30f;
            }
        }

        // online softmax
        float mx0 = -1e30f, mx1 = -1e30f;
#pragma unroll
        for (int nb = 0; nb < 8; nb++) {
            mx0 = fmaxf(mx0, fmaxf(s[nb][0], s[nb][1]));
            mx1 = fmaxf(mx1, fmaxf(s[nb][2], s[nb][3]));
        }
        mx0 = fmaxf(mx0, __shfl_xor_sync(0xffffffffu, mx0, 1));
        mx0 = fmaxf(mx0, __shfl_xor_sync(0xffffffffu, mx0, 2));
        mx1 = fmaxf(mx1, __shfl_xor_sync(0xffffffffu, mx1, 1));
        mx1 = fmaxf(mx1, __shfl_xor_sync(0xffffffffu, mx1, 2));

        float m0n = fmaxf(m0, mx0), m1n = fmaxf(m1, mx1);
        float f0 = __expf(m0 - m0n), f1 = __expf(m1 - m1n);

        float sum0 = 0.f, sum1 = 0.f;
#pragma unroll
        for (int nb = 0; nb < 8; nb++) {
            s[nb][0] = __expf(s[nb][0] - m0n);
            s[nb][1] = __expf(s[nb][1] - m0n);
            s[nb][2] = __expf(s[nb][2] - m1n);
            s[nb][3] = __expf(s[nb][3] - m1n);
            sum0 += s[nb][0] + s[nb][1];
            sum1 += s[nb][2] + s[nb][3];
        }
        sum0 += __shfl_xor_sync(0xffffffffu, sum0, 1);
        sum0 += __shfl_xor_sync(0xffffffffu, sum0, 2);
        sum1 += __shfl_xor_sync(0xffffffffu, sum1, 1);
        sum1 += __shfl_xor_sync(0xffffffffu, sum1, 2);

        m0 = m0n; m1 = m1n;
        l0 = l0 * f0 + sum0;
        l1 = l1 * f1 + sum1;

#pragma unroll
        for (int d = 0; d < 16; d++) {
            oa[d][0] *= f0; oa[d][1] *= f0;
            oa[d][2] *= f1; oa[d][3] *= f1;
        }

        // P -> fp16 A-frags (hi only)
        uint32_t Ph[4][4];
#pragma unroll
        for (int kk2 = 0; kk2 < 4; kk2++) {
            int nb = 2 * kk2;
#pragma unroll
            for (int half = 0; half < 2; half++) {
                int src = nb + half;
                __half2 hA = __floats2half2_rn(s[src][0], s[src][1]);
                __half2 hB = __floats2half2_rn(s[src][2], s[src][3]);
                Ph[kk2][half * 2 + 0] = *(uint32_t*)&hA;
                Ph[kk2][half * 2 + 1] = *(uint32_t*)&hB;
            }
        }

        // ===== O += Ph @ Vh (single pass) =====
#pragma unroll
        for (int kk2 = 0; kk2 < 4; kk2++) {
#pragma unroll
            for (int dp = 0; dp < 8; dp++) {
                uint32_t voff = ((uint32_t)(kk2 * 16) + lrow) * 272u
                              + (uint32_t)dp * 32u + lseg16;
                uint32_t h0, h1, h2, h3;
                ldmx4t(vb + voff, h0, h1, h2, h3);
                int dnb = dp * 2;
                mma16816(oa[dnb][0], oa[dnb][1], oa[dnb][2], oa[dnb][3],
                         Ph[kk2][0], Ph[kk2][1], Ph[kk2][2], Ph[kk2][3], h0, h1);
                mma16816(oa[dnb + 1][0], oa[dnb + 1][1], oa[dnb + 1][2], oa[dnb + 1][3],
                         Ph[kk2][0], Ph[kk2][1], Ph[kk2][2], Ph[kk2][3], h2, h3);
            }
        }
    }

    // epilogue: normalize, store fp16 (hi only)
    float inv0 = 1.0f / l0, inv1 = 1.0f / l1;
    int r0 = i0 + warp * 16 + g;
    __half* ohb = oh + hoff;
#pragma unroll
    for (int dnb = 0; dnb < 16; dnb++) {
        int col = dnb * 8 + 2 * q4;
        __half2 h0 = __floats2half2_rn(oa[dnb][0] * inv0, oa[dnb][1] * inv0);
        __half2 h1 = __floats2half2_rn(oa[dnb][2] * inv1, oa[dnb][3] * inv1);
        *(__half2*)&ohb[(size_t)r0 * DMODEL + col] = h0;
        *(__half2*)&ohb[(size_t)(r0 + 8) * DMODEL + col] = h1;
    }
}

// ---------------------------------------------------------------------------
extern "C" void kernel_launch(void* const* d_in, const int* in_sizes, int n_in,
                              void* d_out, int out_size)
{
    const float* x  = (const float*)d_in[0];
    const float* Wq = (const float*)d_in[1];
    const float* bq = (const float*)d_in[2];
    const float* Wk = (const float*)d_in[3];
    const float* bk = (const float*)d_in[4];
    const float* Wv = (const float*)d_in[5];
    const float* bv = (const float*)d_in[6];
    const float* Wo = (const float*)d_in[7];
    const float* bo = (const float*)d_in[8];
    float* out = (float*)d_out;

    __half *xhi, *ahi, *qhh, *khh, *vhh;
    __half *wq, *wk, *wv, *wo;
    cudaGetSymbolAddress((void**)&xhi, g_xhi);
    cudaGetSymbolAddress((void**)&ahi, g_ahi);
    cudaGetSymbolAddress((void**)&qhh, g_qh);
    cudaGetSymbolAddress((void**)&khh, g_kh);
    cudaGetSymbolAddress((void**)&vhh, g_vh);
    cudaGetSymbolAddress((void**)&wq, g_wq);
    cudaGetSymbolAddress((void**)&wk, g_wk);
    cudaGetSymbolAddress((void**)&wv, g_wv);
    cudaGetSymbolAddress((void**)&wo, g_wo);

    cudaFuncSetAttribute(gemm_qkv, cudaFuncAttributeMaxDynamicSharedMemorySize, GEMM1_SMEM);
    cudaFuncSetAttribute(gemm_1p, cudaFuncAttributeMaxDynamicSharedMemorySize, GEMM1_SMEM);
    cudaFuncSetAttribute(flash_attn_mma, cudaFuncAttributeMaxDynamicSharedMemorySize, ATT_SMEM);

    // prep: convert x, transpose+convert weights
    int n4x = ROWS * DMODEL / 4;
    cvt_kernel<<<(n4x + 255) / 256, 256>>>((const float4*)x, xhi, n4x);
    dim3 tgrid(DMODEL / 32, DMODEL / 32, 4);
    transpose_cvt4<<<tgrid, 256>>>(Wq, Wk, Wv, Wo, wq, wk, wv, wo);

    // fused QKV projection (single pass) + rotary
    dim3 qkv_grid(3 * DMODEL / TN, ROWS / TM);   // (48, 32)
    gemm_qkv<<<qkv_grid, 256, GEMM1_SMEM>>>(xhi, wq, wk, wv,
                                            bq, bk, bv, qhh, khh, vhh);

    // tensor-core flash attention (fully single pass)
    dim3 attn_grid(NSEQ / 64, BATCH * HEADS);   // (32, 32)
    flash_attn_mma<<<attn_grid, 128, ATT_SMEM>>>(qhh, khh, vhh, ahi);

    // output projection (single pass)
    dim3 ggrid(DMODEL / TN, ROWS / TM);   // (16, 32)
    gemm_1p<<<ggrid, 256, GEMM1_SMEM>>>(ahi, wo, bo, out);
}

// round 14
// speedup vs baseline: 1.8128x; 1.0044x over previous
#include <cuda_runtime.h>
#include <cuda_fp16.h>
#include <math.h>
#include <stdint.h>

#define BATCH 2
#define NSEQ  2048
#define DMODEL 2048
#define HEADS 16
#define DHEAD 128
#define ROWS (BATCH*NSEQ)   // 4096

// ---------------------------------------------------------------------------
// scratch (device globals: no allocation allowed)
// ---------------------------------------------------------------------------
__device__ __half g_xhi[ROWS*DMODEL];
__device__ __half g_ahi[ROWS*DMODEL];
__device__ __half g_qh[ROWS*DMODEL];
__device__ __half g_kh[ROWS*DMODEL];
__device__ __half g_vh[ROWS*DMODEL];
__device__ __half g_wq[DMODEL*DMODEL];
__device__ __half g_wk[DMODEL*DMODEL];
__device__ __half g_wv[DMODEL*DMODEL];
__device__ __half g_wo[DMODEL*DMODEL];

// ---------------------------------------------------------------------------
// helpers
// ---------------------------------------------------------------------------
__device__ __forceinline__ uint32_t smem_u32(const void* p) {
    uint32_t a;
    asm("{ .reg .u64 t; cvta.to.shared.u64 t, %1; cvt.u32.u64 %0, t; }" : "=r"(a) : "l"(p));
    return a;
}

__device__ __forceinline__ void cp16(uint32_t dst, const void* src) {
    asm volatile("cp.async.cg.shared.global [%0], [%1], 16;" :: "r"(dst), "l"(src));
}
#define CP_COMMIT() asm volatile("cp.async.commit_group;" ::: "memory")
#define CP_WAIT(n)  asm volatile("cp.async.wait_group %0;" :: "n"(n) : "memory")

__device__ __forceinline__ void ldmx4(uint32_t addr, uint32_t& r0, uint32_t& r1,
                                      uint32_t& r2, uint32_t& r3) {
    asm volatile("ldmatrix.sync.aligned.m8n8.x4.shared.b16 {%0,%1,%2,%3}, [%4];"
                 : "=r"(r0), "=r"(r1), "=r"(r2), "=r"(r3) : "r"(addr));
}
__device__ __forceinline__ void ldmx4t(uint32_t addr, uint32_t& r0, uint32_t& r1,
                                       uint32_t& r2, uint32_t& r3) {
    asm volatile("ldmatrix.sync.aligned.m8n8.x4.trans.shared.b16 {%0,%1,%2,%3}, [%4];"
                 : "=r"(r0), "=r"(r1), "=r"(r2), "=r"(r3) : "r"(addr));
}

// fp16 inputs, fp32 accumulate
__device__ __forceinline__ void mma16816(float& c0, float& c1, float& c2, float& c3,
                                         uint32_t a0, uint32_t a1, uint32_t a2, uint32_t a3,
                                         uint32_t b0, uint32_t b1) {
    asm volatile(
        "mma.sync.aligned.m16n8k16.row.col.f32.f16.f16.f32 "
        "{%0,%1,%2,%3}, {%4,%5,%6,%7}, {%8,%9}, {%0,%1,%2,%3};"
        : "+f"(c0), "+f"(c1), "+f"(c2), "+f"(c3)
        : "r"(a0), "r"(a1), "r"(a2), "r"(a3), "r"(b0), "r"(b1));
}

// ---------------------------------------------------------------------------
// convert: fp32 -> fp16 (hi only)
// ---------------------------------------------------------------------------
__global__ __launch_bounds__(256)
void cvt_kernel(const float4* __restrict__ in, __half* __restrict__ hi, int n4)
{
    int i = blockIdx.x * 256 + threadIdx.x;
    if (i >= n4) return;
    float4 v = in[i];
    __half2* hp = (__half2*)(hi + 4 * (size_t)i);
    hp[0] = __floats2half2_rn(v.x, v.y);
    hp[1] = __floats2half2_rn(v.z, v.w);
}

// ---------------------------------------------------------------------------
// transpose + convert: W[K][N] fp32 -> Wt[N][K] fp16 (hi only), 4 weights
// ---------------------------------------------------------------------------
__global__ __launch_bounds__(256)
void transpose_cvt4(const float* __restrict__ W0, const float* __restrict__ W1,
                    const float* __restrict__ W2, const float* __restrict__ W3,
                    __half* __restrict__ t0, __half* __restrict__ t1,
                    __half* __restrict__ t2, __half* __restrict__ t3)
{
    int z = blockIdx.z;
    const float* W = (z == 0) ? W0 : (z == 1) ? W1 : (z == 2) ? W2 : W3;
    __half* th = (z == 0) ? t0 : (z == 1) ? t1 : (z == 2) ? t2 : t3;

    __shared__ float t[32][33];
    int n0 = blockIdx.x * 32, k0 = blockIdx.y * 32;
    int tx = threadIdx.x & 31, ty = threadIdx.x >> 5;
#pragma unroll
    for (int i = 0; i < 32; i += 8)
        t[ty + i][tx] = W[(size_t)(k0 + ty + i) * DMODEL + n0 + tx];
    __syncthreads();
#pragma unroll
    for (int i = 0; i < 32; i += 8)
        th[(size_t)(n0 + ty + i) * DMODEL + k0 + tx] = __float2half(t[tx][ty + i]);
}

// ---------------------------------------------------------------------------
// GEMM config: CTA 128x128, 256 threads, warp tile 64x32, KC=64, single-pass
// ---------------------------------------------------------------------------
#define GK DMODEL
#define TM 128
#define TN 128
#define KC 64
#define RSTRB 144u                     // bytes per smem row (128 data + 16 pad)
#define TILE_B (128u * RSTRB)          // 18432
#define STAGE1_B (2u * TILE_B)         // 36864 (Ah, Bh)
#define GEMM1_SMEM (2u * STAGE1_B)     // 73728

// single-pass mainloop shared by both GEMMs (needs: sb, tid, wid, lane, wm, wn,
// Ahi, Bhh, brow, bcol, acc). copy-before-wait double buffering.
#define GEMM1_BODY(ACC)                                                                 \
    auto copy_chunk = [&](int c, int stg) {                                             \
        int k0 = c * KC;                                                                \
        uint32_t base = sb + (uint32_t)stg * STAGE1_B;                                  \
        const __half* srcs[2] = { Ahi, Bhh };                                           \
        int rows0[2] = { brow, bcol };                                                  \
        _Pragma("unroll")                                                               \
        for (int t = 0; t < 2; t++) {                                                   \
            const __half* src = srcs[t] + (size_t)rows0[t] * GK + k0;                   \
            uint32_t tb = base + (uint32_t)t * TILE_B;                                  \
            _Pragma("unroll")                                                           \
            for (int i = 0; i < 4; i++) {                                               \
                int s = i * 256 + tid;                                                  \
                int r = s >> 3, seg = s & 7;                                            \
                cp16(tb + (uint32_t)r * RSTRB + (uint32_t)seg * 16u,                    \
                     src + (size_t)r * GK + seg * 8);                                   \
            }                                                                           \
        }                                                                               \
        CP_COMMIT();                                                                    \
    };                                                                                  \
    const int NCH = GK / KC;                                                            \
    copy_chunk(0, 0);                                                                   \
    const uint32_t lrow = (uint32_t)(lane & 15);                                        \
    const uint32_t lcol2 = (uint32_t)((lane >> 4) & 1) * 16u;                           \
    for (int c = 0; c < NCH; c++) {                                                     \
        int stg = c & 1;                                                                \
        if (c + 1 < NCH) {                                                              \
            copy_chunk(c + 1, stg ^ 1);                                                 \
            CP_WAIT(1);                                                                 \
        } else {                                                                        \
            CP_WAIT(0);                                                                 \
        }                                                                               \
        __syncthreads();                                                                \
        uint32_t base = sb + (uint32_t)stg * STAGE1_B;                                  \
        uint32_t ah_b = base;                                                           \
        uint32_t bh_b = base + TILE_B;                                                  \
        _Pragma("unroll")                                                               \
        for (int kk = 0; kk < 4; kk++) {                                                \
            uint32_t koff = (uint32_t)kk * 32u + lcol2;                                 \
            uint32_t Ah[4][4];                                                          \
            _Pragma("unroll")                                                           \
            for (int mi = 0; mi < 4; mi++) {                                            \
                uint32_t roff = ((uint32_t)(wm * 64 + mi * 16) + lrow) * RSTRB + koff;  \
                ldmx4(ah_b + roff, Ah[mi][0], Ah[mi][1], Ah[mi][2], Ah[mi][3]);         \
            }                                                                           \
            uint32_t Bh[4][2];                                                          \
            _Pragma("unroll")                                                           \
            for (int np = 0; np < 2; np++) {                                            \
                uint32_t roff = ((uint32_t)(wn * 32 + np * 16) + lrow) * RSTRB + koff;  \
                uint32_t r0, r1, r2, r3;                                                \
                ldmx4(bh_b + roff, r0, r1, r2, r3);                                     \
                Bh[np * 2][0] = r0; Bh[np * 2 + 1][0] = r1;                             \
                Bh[np * 2][1] = r2; Bh[np * 2 + 1][1] = r3;                             \
            }                                                                           \
            _Pragma("unroll")                                                           \
            for (int mi = 0; mi < 4; mi++)                                              \
                _Pragma("unroll")                                                       \
                for (int ni = 0; ni < 4; ni++)                                          \
                    mma16816(ACC[mi][ni][0], ACC[mi][ni][1], ACC[mi][ni][2], ACC[mi][ni][3], \
                             Ah[mi][0], Ah[mi][1], Ah[mi][2], Ah[mi][3],                \
                             Bh[ni][0], Bh[ni][1]);                                     \
        }                                                                               \
        __syncthreads();                                                                \
    }

// ---------------------------------------------------------------------------
// Fused QKV GEMM (single pass) + rotary + fp16 epilogue. grid (48, 32).
// All outputs stored hi-only.
// ---------------------------------------------------------------------------
__global__ __launch_bounds__(256, 2)
void gemm_qkv(const __half* __restrict__ xhi,
              const __half* __restrict__ wq, const __half* __restrict__ wk,
              const __half* __restrict__ wv,
              const float* __restrict__ bq, const float* __restrict__ bk,
              const float* __restrict__ bv,
              __half* __restrict__ qh, __half* __restrict__ kh, __half* __restrict__ vh)
{
    extern __shared__ __align__(128) char smem[];
    uint32_t sb = smem_u32(smem);
    const int tid  = threadIdx.x;
    const int wid  = tid >> 5;
    const int lane = tid & 31;
    const int brow = blockIdx.y * TM;
    const int mtx  = blockIdx.x >> 4;
    const int bcol = (blockIdx.x & 15) * TN;

    const __half* Ahi = xhi;
    const __half* Bhh = (mtx == 0) ? wq : (mtx == 1) ? wk : wv;
    const float* bias = (mtx == 0) ? bq : (mtx == 1) ? bk : bv;
    __half* Oh        = (mtx == 0) ? qh : (mtx == 1) ? kh : vh;

    const int wm = wid & 1;
    const int wn = wid >> 1;

    float acc[4][4][4];
#pragma unroll
    for (int i = 0; i < 4; i++)
#pragma unroll
        for (int j = 0; j < 4; j++)
#pragma unroll
            for (int r = 0; r < 4; r++) acc[i][j][r] = 0.f;

    GEMM1_BODY(acc)

    // ------ fused epilogue: stage fp32 tile in smem, rotary, store hi ----
    float* ft = (float*)smem;    // [128][132] fp32 = 67584 B (< 73728)
    int g = lane >> 2, t4 = lane & 3;
#pragma unroll
    for (int mi = 0; mi < 4; mi++) {
        int r0 = wm * 64 + mi * 16 + g;
#pragma unroll
        for (int ni = 0; ni < 4; ni++) {
            int cl = wn * 32 + ni * 8 + 2 * t4;
            float2 b01 = *(const float2*)&bias[bcol + cl];
            *(float2*)&ft[r0 * 132 + cl] =
                make_float2(acc[mi][ni][0] + b01.x, acc[mi][ni][1] + b01.y);
            *(float2*)&ft[(r0 + 8) * 132 + cl] =
                make_float2(acc[mi][ni][2] + b01.x, acc[mi][ni][3] + b01.y);
        }
    }
    __syncthreads();

    const bool  do_rot = (mtx < 2);
    const float scale  = (mtx == 0) ? 0.08838834764831845f : 1.0f;
    int d  = tid & 63;
    int rb = tid >> 6;
    float inv_freq = __expf(-(float)d * (9.210340371976184f / 64.0f));

    for (int rr = rb; rr < 128; rr += 4) {
        int grow = brow + rr;
        float a = ft[rr * 132 + d];
        float b2 = ft[rr * 132 + d + 64];
        float oa, ob2;
        if (do_rot) {
            int n = grow & (NSEQ - 1);
            float s, c;
            sincosf((float)n * inv_freq, &s, &c);
            oa  = (a * c - b2 * s) * scale;
            ob2 = (b2 * c + a * s) * scale;
        } else {
            oa = a; ob2 = b2;
        }
        size_t base = (size_t)grow * DMODEL + bcol + d;
        Oh[base]      = __float2half(oa);
        Oh[base + 64] = __float2half(ob2);
    }
}

// ---------------------------------------------------------------------------
// Out projection GEMM (single pass), fp32 output + bias
// ---------------------------------------------------------------------------
__global__ __launch_bounds__(256, 2)
void gemm_1p(const __half* __restrict__ Ahi, const __half* __restrict__ Bhh,
             const float* __restrict__ bias, float* __restrict__ C)
{
    extern __shared__ __align__(128) char smem[];
    uint32_t sb = smem_u32(smem);
    const int tid  = threadIdx.x;
    const int wid  = tid >> 5;
    const int lane = tid & 31;
    const int brow = blockIdx.y * TM;
    const int bcol = blockIdx.x * TN;

    const int wm = wid & 1;
    const int wn = wid >> 1;

    float acc[4][4][4];
#pragma unroll
    for (int i = 0; i < 4; i++)
#pragma unroll
        for (int j = 0; j < 4; j++)
#pragma unroll
            for (int r = 0; r < 4; r++) acc[i][j][r] = 0.f;

    GEMM1_BODY(acc)

    int g = lane >> 2, t4 = lane & 3;
#pragma unroll
    for (int mi = 0; mi < 4; mi++) {
        int r0 = brow + wm * 64 + mi * 16 + g;
#pragma unroll
        for (int ni = 0; ni < 4; ni++) {
            int col = bcol + wn * 32 + ni * 8 + 2 * t4;
            float2 b01 = *(const float2*)&bias[col];
            float2 o0, o1;
            o0.x = acc[mi][ni][0] + b01.x;
            o0.y = acc[mi][ni][1] + b01.y;
            o1.x = acc[mi][ni][2] + b01.x;
            o1.y = acc[mi][ni][3] + b01.y;
            *(float2*)&C[(size_t)r0 * DMODEL + col]       = o0;
            *(float2*)&C[(size_t)(r0 + 8) * DMODEL + col] = o1;
        }
    }
}

// ---------------------------------------------------------------------------
// Flash attention (causal), fully single-pass fp16: S=Qh*Kh, O=Ph*Vh.
// BR=BC=64, 128 threads, Q in regs, 4 rotating K/V buffers.
// __launch_bounds__(128, 3): cap regs at 170 -> 3 CTAs/SM (12 warps) to hide
// the serial softmax chains inside other CTAs' mma streams.
// ---------------------------------------------------------------------------
#define ABUF_B 17408u
#define ATT_SMEM (4u * ABUF_B)        // 69632 (3 CTAs = 208896 <= 228KB)

__global__ __launch_bounds__(128, 3)
void flash_attn_mma(const __half* __restrict__ qh, const __half* __restrict__ kh,
                    const __half* __restrict__ vh, __half* __restrict__ oh)
{
    extern __shared__ __align__(128) char smem[];
    uint32_t sb = smem_u32(smem);

    const int tid  = threadIdx.x;
    const int warp = tid >> 5;
    const int lane = tid & 31;
    const int g    = lane >> 2;
    const int q4   = lane & 3;

    const int it = gridDim.x - 1 - blockIdx.x;   // heavy tiles first
    const int bh = blockIdx.y;
    const int b = bh >> 4, h = bh & 15;
    const int i0 = it * 64;

    const size_t hoff = (size_t)b * NSEQ * DMODEL + h * DHEAD;
    const __half* qhb = qh + hoff;
    const __half* khb = kh + hoff;
    const __half* vhb = vh + hoff;

    auto copyTile = [&](const __half* src, int row0, uint32_t buf) {
#pragma unroll
        for (int i = 0; i < 8; i++) {
            int s = i * 128 + tid;
            int r = s >> 4, seg = s & 15;
            cp16(buf + (uint32_t)r * 272u + (uint32_t)seg * 16u,
                 src + (size_t)(row0 + r) * DMODEL + seg * 8);
        }
    };

    uint32_t K0 = sb, K1 = sb + ABUF_B, V0 = sb + 2u * ABUF_B, V1 = sb + 3u * ABUF_B;

    // stage Q in K1 (freed before jt=1 needs it), then KV(0)
    copyTile(qhb, i0, K1);
    CP_COMMIT();
    copyTile(khb, 0, K0);
    copyTile(vhb, 0, V0);
    CP_COMMIT();

    CP_WAIT(1);                 // Q done
    __syncthreads();

    const uint32_t lrow = (uint32_t)(lane & 15);
    const uint32_t lseg16 = (uint32_t)(lane >> 4) * 16u;
    uint32_t Qh4[8][4];
#pragma unroll
    for (int kk = 0; kk < 8; kk++) {
        uint32_t qoff = ((uint32_t)(warp * 16) + lrow) * 272u + lseg16 + (uint32_t)kk * 32u;
        ldmx4(K1 + qoff, Qh4[kk][0], Qh4[kk][1], Qh4[kk][2], Qh4[kk][3]);
    }

    float m0 = -1e30f, m1 = -1e30f, l0 = 0.f, l1 = 0.f;
    float oa[16][4];
#pragma unroll
    for (int d = 0; d < 16; d++)
#pragma unroll
        for (int r = 0; r < 4; r++) oa[d][r] = 0.f;

    const int NJT = it + 1;

    for (int jt = 0; jt < NJT; jt++) {
        int stg = jt & 1;
        uint32_t kb = stg ? K1 : K0;
        uint32_t vb = stg ? V1 : V0;

        CP_WAIT(0);
        __syncthreads();        // all warps done with previous buffers / Q frags
        if (jt + 1 < NJT) {
            copyTile(khb, (jt + 1) * 64, stg ? K0 : K1);
            copyTile(vhb, (jt + 1) * 64, stg ? V0 : V1);
            CP_COMMIT();
        }

        // ===== S = Qh @ Kh^T (single pass) =====
        float s[8][4];
#pragma unroll
        for (int nb = 0; nb < 8; nb++)
#pragma unroll
            for (int r = 0; r < 4; r++) s[nb][r] = 0.f;

#pragma unroll
        for (int kk = 0; kk < 8; kk++) {
#pragma unroll
            for (int np = 0; np < 4; np++) {
                uint32_t koff = ((uint32_t)(np * 16) + lrow) * 272u + lseg16 + (uint32_t)kk * 32u;
                uint32_t h0, h1, h2, h3;
                ldmx4(kb + koff, h0, h1, h2, h3);
                int nb = np * 2;
                mma16816(s[nb][0], s[nb][1], s[nb][2], s[nb][3],
                         Qh4[kk][0], Qh4[kk][1], Qh4[kk][2], Qh4[kk][3], h0, h2);
                mma16816(s[nb + 1][0], s[nb + 1][1], s[nb + 1][2], s[nb + 1][3],
                         Qh4[kk][0], Qh4[kk][1], Qh4[kk][2], Qh4[kk][3], h1, h3);
            }
        }

        // causal mask on diagonal tile
        if (jt == it) {
            int r0 = warp * 16 + g;
            int r1 = r0 + 8;
#pragma unroll
            for (int nb = 0; nb < 8; nb++) {
                int c0 = nb * 8 + 2 * q4;
                if (c0 > r0)     s[nb][0] = -1e30f;
                if (c0 + 1 > r0) s[nb][1] = -1e30f;
                if (c0 > r1)     s[nb][2] = -1e30f;
                if (c0 + 1 > r1) s[nb][3] = -1e30f;
            }
        }

        // online softmax
        float mx0 = -1e30f, mx1 = -1e30f;
#pragma unroll
        for (int nb = 0; nb < 8; nb++) {
            mx0 = fmaxf(mx0, fmaxf(s[nb][0], s[nb][1]));
            mx1 = fmaxf(mx1, fmaxf(s[nb][2], s[nb][3]));
        }
        mx0 = fmaxf(mx0, __shfl_xor_sync(0xffffffffu, mx0, 1));
        mx0 = fmaxf(mx0, __shfl_xor_sync(0xffffffffu, mx0, 2));
        mx1 = fmaxf(mx1, __shfl_xor_sync(0xffffffffu, mx1, 1));
        mx1 = fmaxf(mx1, __shfl_xor_sync(0xffffffffu, mx1, 2));

        float m0n = fmaxf(m0, mx0), m1n = fmaxf(m1, mx1);
        float f0 = __expf(m0 - m0n), f1 = __expf(m1 - m1n);

        float sum0 = 0.f, sum1 = 0.f;
#pragma unroll
        for (int nb = 0; nb < 8; nb++) {
            s[nb][0] = __expf(s[nb][0] - m0n);
            s[nb][1] = __expf(s[nb][1] - m0n);
            s[nb][2] = __expf(s[nb][2] - m1n);
            s[nb][3] = __expf(s[nb][3] - m1n);
            sum0 += s[nb][0] + s[nb][1];
            sum1 += s[nb][2] + s[nb][3];
        }
        sum0 += __shfl_xor_sync(0xffffffffu, sum0, 1);
        sum0 += __shfl_xor_sync(0xffffffffu, sum0, 2);
        sum1 += __shfl_xor_sync(0xffffffffu, sum1, 1);
        sum1 += __shfl_xor_sync(0xffffffffu, sum1, 2);

        m0 = m0n; m1 = m1n;
        l0 = l0 * f0 + sum0;
        l1 = l1 * f1 + sum1;

#pragma unroll
        for (int d = 0; d < 16; d++) {
            oa[d][0] *= f0; oa[d][1] *= f0;
            oa[d][2] *= f1; oa[d][3] *= f1;
        }

        // P -> fp16 A-frags (hi only)
        uint32_t Ph[4][4];
#pragma unroll
        for (int kk2 = 0; kk2 < 4; kk2++) {
            int nb = 2 * kk2;
#pragma unroll
            for (int half = 0; half < 2; half++) {
                int src = nb + half;
                __half2 hA = __floats2half2_rn(s[src][0], s[src][1]);
                __half2 hB = __floats2half2_rn(s[src][2], s[src][3]);
                Ph[kk2][half * 2 + 0] = *(uint32_t*)&hA;
                Ph[kk2][half * 2 + 1] = *(uint32_t*)&hB;
            }
        }

        // ===== O += Ph @ Vh (single pass) =====
#pragma unroll
        for (int kk2 = 0; kk2 < 4; kk2++) {
#pragma unroll
            for (int dp = 0; dp < 8; dp++) {
                uint32_t voff = ((uint32_t)(kk2 * 16) + lrow) * 272u
                              + (uint32_t)dp * 32u + lseg16;
                uint32_t h0, h1, h2, h3;
                ldmx4t(vb + voff, h0, h1, h2, h3);
                int dnb = dp * 2;
                mma16816(oa[dnb][0], oa[dnb][1], oa[dnb][2], oa[dnb][3],
                         Ph[kk2][0], Ph[kk2][1], Ph[kk2][2], Ph[kk2][3], h0, h1);
                mma16816(oa[dnb + 1][0], oa[dnb + 1][1], oa[dnb + 1][2], oa[dnb + 1][3],
                         Ph[kk2][0], Ph[kk2][1], Ph[kk2][2], Ph[kk2][3], h2, h3);
            }
        }
    }

    // epilogue: normalize, store fp16 (hi only)
    float inv0 = 1.0f / l0, inv1 = 1.0f / l1;
    int r0 = i0 + warp * 16 + g;
    __half* ohb = oh + hoff;
#pragma unroll
    for (int dnb = 0; dnb < 16; dnb++) {
        int col = dnb * 8 + 2 * q4;
        __half2 h0 = __floats2half2_rn(oa[dnb][0] * inv0, oa[dnb][1] * inv0);
        __half2 h1 = __floats2half2_rn(oa[dnb][2] * inv1, oa[dnb][3] * inv1);
        *(__half2*)&ohb[(size_t)r0 * DMODEL + col] = h0;
        *(__half2*)&ohb[(size_t)(r0 + 8) * DMODEL + col] = h1;
    }
}

// ---------------------------------------------------------------------------
extern "C" void kernel_launch(void* const* d_in, const int* in_sizes, int n_in,
                              void* d_out, int out_size)
{
    const float* x  = (const float*)d_in[0];
    const float* Wq = (const float*)d_in[1];
    const float* bq = (const float*)d_in[2];
    const float* Wk = (const float*)d_in[3];
    const float* bk = (const float*)d_in[4];
    const float* Wv = (const float*)d_in[5];
    const float* bv = (const float*)d_in[6];
    const float* Wo = (const float*)d_in[7];
    const float* bo = (const float*)d_in[8];
    float* out = (float*)d_out;

    __half *xhi, *ahi, *qhh, *khh, *vhh;
    __half *wq, *wk, *wv, *wo;
    cudaGetSymbolAddress((void**)&xhi, g_xhi);
    cudaGetSymbolAddress((void**)&ahi, g_ahi);
    cudaGetSymbolAddress((void**)&qhh, g_qh);
    cudaGetSymbolAddress((void**)&khh, g_kh);
    cudaGetSymbolAddress((void**)&vhh, g_vh);
    cudaGetSymbolAddress((void**)&wq, g_wq);
    cudaGetSymbolAddress((void**)&wk, g_wk);
    cudaGetSymbolAddress((void**)&wv, g_wv);
    cudaGetSymbolAddress((void**)&wo, g_wo);

    cudaFuncSetAttribute(gemm_qkv, cudaFuncAttributeMaxDynamicSharedMemorySize, GEMM1_SMEM);
    cudaFuncSetAttribute(gemm_1p, cudaFuncAttributeMaxDynamicSharedMemorySize, GEMM1_SMEM);
    cudaFuncSetAttribute(flash_attn_mma, cudaFuncAttributeMaxDynamicSharedMemorySize, ATT_SMEM);

    // prep: convert x, transpose+convert weights
    int n4x = ROWS * DMODEL / 4;
    cvt_kernel<<<(n4x + 255) / 256, 256>>>((const float4*)x, xhi, n4x);
    dim3 tgrid(DMODEL / 32, DMODEL / 32, 4);
    transpose_cvt4<<<tgrid, 256>>>(Wq, Wk, Wv, Wo, wq, wk, wv, wo);

    // fused QKV projection (single pass) + rotary
    dim3 qkv_grid(3 * DMODEL / TN, ROWS / TM);   // (48, 32)
    gemm_qkv<<<qkv_grid, 256, GEMM1_SMEM>>>(xhi, wq, wk, wv,
                                            bq, bk, bv, qhh, khh, vhh);

    // tensor-core flash attention (fully single pass, 3 CTAs/SM)
    dim3 attn_grid(NSEQ / 64, BATCH * HEADS);   // (32, 32)
    flash_attn_mma<<<attn_grid, 128, ATT_SMEM>>>(qhh, khh, vhh, ahi);

    // output projection (single pass)
    dim3 ggrid(DMODEL / TN, ROWS / TM);   // (16, 32)
    gemm_1p<<<ggrid, 256, GEMM1_SMEM>>>(ahi, wo, bo, out);
}

// round 15
// speedup vs baseline: 2.2427x; 1.2371x over previous
#include <cuda_runtime.h>
#include <cuda_fp16.h>
#include <math.h>
#include <stdint.h>

#define BATCH 2
#define NSEQ  2048
#define DMODEL 2048
#define HEADS 16
#define DHEAD 128
#define ROWS (BATCH*NSEQ)   // 4096

// ---------------------------------------------------------------------------
// scratch (device globals: no allocation allowed)
// ---------------------------------------------------------------------------
__device__ __half g_xhi[ROWS*DMODEL];
__device__ __half g_ahi[ROWS*DMODEL];
__device__ __half g_qh[ROWS*DMODEL];
__device__ __half g_kh[ROWS*DMODEL];
__device__ __half g_vh[ROWS*DMODEL];
__device__ __half g_wq[DMODEL*DMODEL];   // row-major [K][N] fp16
__device__ __half g_wk[DMODEL*DMODEL];
__device__ __half g_wv[DMODEL*DMODEL];
__device__ __half g_wo[DMODEL*DMODEL];

// ---------------------------------------------------------------------------
// helpers
// ---------------------------------------------------------------------------
__device__ __forceinline__ uint32_t smem_u32(const void* p) {
    uint32_t a;
    asm("{ .reg .u64 t; cvta.to.shared.u64 t, %1; cvt.u32.u64 %0, t; }" : "=r"(a) : "l"(p));
    return a;
}

__device__ __forceinline__ void cp16(uint32_t dst, const void* src) {
    asm volatile("cp.async.cg.shared.global [%0], [%1], 16;" :: "r"(dst), "l"(src));
}
#define CP_COMMIT() asm volatile("cp.async.commit_group;" ::: "memory")
#define CP_WAIT(n)  asm volatile("cp.async.wait_group %0;" :: "n"(n) : "memory")

// swizzled offset inside a 256B-stride tile: row r, 16B segment seg
__device__ __forceinline__ uint32_t swz(uint32_t r, uint32_t seg) {
    return r * 256u + ((seg ^ (r & 7u)) << 4);
}

__device__ __forceinline__ void ldmx4(uint32_t addr, uint32_t& r0, uint32_t& r1,
                                      uint32_t& r2, uint32_t& r3) {
    asm volatile("ldmatrix.sync.aligned.m8n8.x4.shared.b16 {%0,%1,%2,%3}, [%4];"
                 : "=r"(r0), "=r"(r1), "=r"(r2), "=r"(r3) : "r"(addr));
}
__device__ __forceinline__ void ldmx4t(uint32_t addr, uint32_t& r0, uint32_t& r1,
                                       uint32_t& r2, uint32_t& r3) {
    asm volatile("ldmatrix.sync.aligned.m8n8.x4.trans.shared.b16 {%0,%1,%2,%3}, [%4];"
                 : "=r"(r0), "=r"(r1), "=r"(r2), "=r"(r3) : "r"(addr));
}

// fp16 inputs, fp32 accumulate
__device__ __forceinline__ void mma16816(float& c0, float& c1, float& c2, float& c3,
                                         uint32_t a0, uint32_t a1, uint32_t a2, uint32_t a3,
                                         uint32_t b0, uint32_t b1) {
    asm volatile(
        "mma.sync.aligned.m16n8k16.row.col.f32.f16.f16.f32 "
        "{%0,%1,%2,%3}, {%4,%5,%6,%7}, {%8,%9}, {%0,%1,%2,%3};"
        : "+f"(c0), "+f"(c1), "+f"(c2), "+f"(c3)
        : "r"(a0), "r"(a1), "r"(a2), "r"(a3), "r"(b0), "r"(b1));
}

// ---------------------------------------------------------------------------
// convert: fp32 -> fp16
// ---------------------------------------------------------------------------
__global__ __launch_bounds__(256)
void cvt_kernel(const float4* __restrict__ in, __half* __restrict__ hi, int n4)
{
    int i = blockIdx.x * 256 + threadIdx.x;
    if (i >= n4) return;
    float4 v = in[i];
    __half2* hp = (__half2*)(hi + 4 * (size_t)i);
    hp[0] = __floats2half2_rn(v.x, v.y);
    hp[1] = __floats2half2_rn(v.z, v.w);
}

// elementwise convert of 4 weight matrices (row-major preserved)
__global__ __launch_bounds__(256)
void cvt_w4(const float* __restrict__ W0, const float* __restrict__ W1,
            const float* __restrict__ W2, const float* __restrict__ W3,
            __half* __restrict__ t0, __half* __restrict__ t1,
            __half* __restrict__ t2, __half* __restrict__ t3)
{
    int z = blockIdx.y;
    const float4* W = (const float4*)((z == 0) ? W0 : (z == 1) ? W1 : (z == 2) ? W2 : W3);
    __half* th = (z == 0) ? t0 : (z == 1) ? t1 : (z == 2) ? t2 : t3;
    int i = blockIdx.x * 256 + threadIdx.x;   // over DMODEL*DMODEL/4
    float4 v = W[i];
    __half2* hp = (__half2*)(th + 4 * (size_t)i);
    hp[0] = __floats2half2_rn(v.x, v.y);
    hp[1] = __floats2half2_rn(v.z, v.w);
}

// ---------------------------------------------------------------------------
// GEMM config: CTA 128x128, 256 threads, warp tile 64x32, KC=64, single-pass.
// A [M][K] in 144B-stride padded tile; B row-major [K][N] in swizzled 256B tile,
// fragments loaded with ldmatrix.trans (mapping proven by the PV path).
// ---------------------------------------------------------------------------
#define GK DMODEL
#define TM 128
#define TN 128
#define KC 64
#define RSTRB 144u                     // A tile: bytes per smem row
#define ATILE_G 18432u                 // 128 * 144
#define BTILE_G 16384u                 // 64 rows * 256B (swizzled)
#define STAGE1_B (ATILE_G + BTILE_G)   // 34816
#define GEMM1_SMEM (2u * STAGE1_B)     // 69632

#define GEMM1_BODY(ACC)                                                                 \
    auto copy_chunk = [&](int c, int stg) {                                             \
        int k0 = c * KC;                                                                \
        uint32_t base = sb + (uint32_t)stg * STAGE1_B;                                  \
        _Pragma("unroll")                                                               \
        for (int i = 0; i < 4; i++) {        /* A: 128 rows x 8 segs */                 \
            int s = i * 256 + tid;                                                      \
            int r = s >> 3, seg = s & 7;                                                \
            cp16(base + (uint32_t)r * RSTRB + (uint32_t)seg * 16u,                      \
                 Ahi + (size_t)(brow + r) * GK + k0 + seg * 8);                         \
        }                                                                               \
        _Pragma("unroll")                                                               \
        for (int i = 0; i < 4; i++) {        /* B: 64 k-rows x 16 segs, swizzled */     \
            int s = i * 256 + tid;                                                      \
            uint32_t r = (uint32_t)(s >> 4), seg = (uint32_t)(s & 15);                  \
            cp16(base + ATILE_G + swz(r, seg),                                          \
                 Bhh + (size_t)(k0 + (int)r) * GK + bcol + seg * 8);                    \
        }                                                                               \
        CP_COMMIT();                                                                    \
    };                                                                                  \
    const int NCH = GK / KC;                                                            \
    copy_chunk(0, 0);                                                                   \
    const uint32_t lrow = (uint32_t)(lane & 15);                                        \
    const uint32_t lhl  = (uint32_t)(lane >> 4);                                        \
    for (int c = 0; c < NCH; c++) {                                                     \
        int stg = c & 1;                                                                \
        if (c + 1 < NCH) {                                                              \
            copy_chunk(c + 1, stg ^ 1);                                                 \
            CP_WAIT(1);                                                                 \
        } else {                                                                        \
            CP_WAIT(0);                                                                 \
        }                                                                               \
        __syncthreads();                                                                \
        uint32_t base = sb + (uint32_t)stg * STAGE1_B;                                  \
        uint32_t ah_b = base;                                                           \
        uint32_t bh_b = base + ATILE_G;                                                 \
        _Pragma("unroll")                                                               \
        for (int kk = 0; kk < 4; kk++) {                                                \
            uint32_t koff = (uint32_t)kk * 32u + lhl * 16u;                             \
            uint32_t Ah[4][4];                                                          \
            _Pragma("unroll")                                                           \
            for (int mi = 0; mi < 4; mi++) {                                            \
                uint32_t roff = ((uint32_t)(wm * 64 + mi * 16) + lrow) * RSTRB + koff;  \
                ldmx4(ah_b + roff, Ah[mi][0], Ah[mi][1], Ah[mi][2], Ah[mi][3]);         \
            }                                                                           \
            uint32_t Bh[4][2];                                                          \
            _Pragma("unroll")                                                           \
            for (int np = 0; np < 2; np++) {                                            \
                uint32_t krow = (uint32_t)(kk * 16) + lrow;                             \
                uint32_t seg  = (uint32_t)(wn * 4 + np * 2) + lhl;                      \
                uint32_t r0, r1, r2, r3;                                                \
                ldmx4t(bh_b + swz(krow, seg), r0, r1, r2, r3);                          \
                Bh[np * 2][0] = r0; Bh[np * 2][1] = r1;                                 \
                Bh[np * 2 + 1][0] = r2; Bh[np * 2 + 1][1] = r3;                         \
            }                                                                           \
            _Pragma("unroll")                                                           \
            for (int mi = 0; mi < 4; mi++)                                              \
                _Pragma("unroll")                                                       \
                for (int ni = 0; ni < 4; ni++)                                          \
                    mma16816(ACC[mi][ni][0], ACC[mi][ni][1], ACC[mi][ni][2], ACC[mi][ni][3], \
                             Ah[mi][0], Ah[mi][1], Ah[mi][2], Ah[mi][3],                \
                             Bh[ni][0], Bh[ni][1]);                                     \
        }                                                                               \
        __syncthreads();                                                                \
    }

// ---------------------------------------------------------------------------
// Fused QKV GEMM (single pass) + rotary + fp16 epilogue. grid (48, 32).
// ---------------------------------------------------------------------------
__global__ __launch_bounds__(256, 2)
void gemm_qkv(const __half* __restrict__ xhi,
              const __half* __restrict__ wq, const __half* __restrict__ wk,
              const __half* __restrict__ wv,
              const float* __restrict__ bq, const float* __restrict__ bk,
              const float* __restrict__ bv,
              __half* __restrict__ qh, __half* __restrict__ kh, __half* __restrict__ vh)
{
    extern __shared__ __align__(128) char smem[];
    uint32_t sb = smem_u32(smem);
    const int tid  = threadIdx.x;
    const int wid  = tid >> 5;
    const int lane = tid & 31;
    const int brow = blockIdx.y * TM;
    const int mtx  = blockIdx.x >> 4;
    const int bcol = (blockIdx.x & 15) * TN;

    const __half* Ahi = xhi;
    const __half* Bhh = (mtx == 0) ? wq : (mtx == 1) ? wk : wv;
    const float* bias = (mtx == 0) ? bq : (mtx == 1) ? bk : bv;
    __half* Oh        = (mtx == 0) ? qh : (mtx == 1) ? kh : vh;

    const int wm = wid & 1;
    const int wn = wid >> 1;

    float acc[4][4][4];
#pragma unroll
    for (int i = 0; i < 4; i++)
#pragma unroll
        for (int j = 0; j < 4; j++)
#pragma unroll
            for (int r = 0; r < 4; r++) acc[i][j][r] = 0.f;

    GEMM1_BODY(acc)

    // ------ fused epilogue: stage fp32 tile in smem, rotary, store hi ----
    float* ft = (float*)smem;    // [128][132] fp32 = 67584 B (< 69632)
    int g = lane >> 2, t4 = lane & 3;
#pragma unroll
    for (int mi = 0; mi < 4; mi++) {
        int r0 = wm * 64 + mi * 16 + g;
#pragma unroll
        for (int ni = 0; ni < 4; ni++) {
            int cl = wn * 32 + ni * 8 + 2 * t4;
            float2 b01 = *(const float2*)&bias[bcol + cl];
            *(float2*)&ft[r0 * 132 + cl] =
                make_float2(acc[mi][ni][0] + b01.x, acc[mi][ni][1] + b01.y);
            *(float2*)&ft[(r0 + 8) * 132 + cl] =
                make_float2(acc[mi][ni][2] + b01.x, acc[mi][ni][3] + b01.y);
        }
    }
    __syncthreads();

    const bool  do_rot = (mtx < 2);
    const float scale  = (mtx == 0) ? 0.08838834764831845f : 1.0f;
    int d  = tid & 63;
    int rb = tid >> 6;
    float inv_freq = __expf(-(float)d * (9.210340371976184f / 64.0f));

    for (int rr = rb; rr < 128; rr += 4) {
        int grow = brow + rr;
        float a = ft[rr * 132 + d];
        float b2 = ft[rr * 132 + d + 64];
        float oa, ob2;
        if (do_rot) {
            int n = grow & (NSEQ - 1);
            float s, c;
            sincosf((float)n * inv_freq, &s, &c);
            oa  = (a * c - b2 * s) * scale;
            ob2 = (b2 * c + a * s) * scale;
        } else {
            oa = a; ob2 = b2;
        }
        size_t base = (size_t)grow * DMODEL + bcol + d;
        Oh[base]      = __float2half(oa);
        Oh[base + 64] = __float2half(ob2);
    }
}

// ---------------------------------------------------------------------------
// Out projection GEMM (single pass), fp32 output + bias
// ---------------------------------------------------------------------------
__global__ __launch_bounds__(256, 2)
void gemm_1p(const __half* __restrict__ Ahi, const __half* __restrict__ Bhh,
             const float* __restrict__ bias, float* __restrict__ C)
{
    extern __shared__ __align__(128) char smem[];
    uint32_t sb = smem_u32(smem);
    const int tid  = threadIdx.x;
    const int wid  = tid >> 5;
    const int lane = tid & 31;
    const int brow = blockIdx.y * TM;
    const int bcol = blockIdx.x * TN;

    const int wm = wid & 1;
    const int wn = wid >> 1;

    float acc[4][4][4];
#pragma unroll
    for (int i = 0; i < 4; i++)
#pragma unroll
        for (int j = 0; j < 4; j++)
#pragma unroll
            for (int r = 0; r < 4; r++) acc[i][j][r] = 0.f;

    GEMM1_BODY(acc)

    int g = lane >> 2, t4 = lane & 3;
#pragma unroll
    for (int mi = 0; mi < 4; mi++) {
        int r0 = brow + wm * 64 + mi * 16 + g;
#pragma unroll
        for (int ni = 0; ni < 4; ni++) {
            int col = bcol + wn * 32 + ni * 8 + 2 * t4;
            float2 b01 = *(const float2*)&bias[col];
            float2 o0, o1;
            o0.x = acc[mi][ni][0] + b01.x;
            o0.y = acc[mi][ni][1] + b01.y;
            o1.x = acc[mi][ni][2] + b01.x;
            o1.y = acc[mi][ni][3] + b01.y;
            *(float2*)&C[(size_t)r0 * DMODEL + col]       = o0;
            *(float2*)&C[(size_t)(r0 + 8) * DMODEL + col] = o1;
        }
    }
}

// ---------------------------------------------------------------------------
// Flash attention (causal), single-pass fp16, swizzled 256B-stride buffers
// (ABUF 16384B; 4 buffers = 64KB -> 3 CTAs/SM). Q in regs, heavy tiles first.
// ---------------------------------------------------------------------------
#define ABUF_B 16384u
#define ATT_SMEM (4u * ABUF_B)        // 65536; 3 CTAs = 196608

__global__ __launch_bounds__(128, 3)
void flash_attn_mma(const __half* __restrict__ qh, const __half* __restrict__ kh,
                    const __half* __restrict__ vh, __half* __restrict__ oh)
{
    extern __shared__ __align__(128) char smem[];
    uint32_t sb = smem_u32(smem);

    const int tid  = threadIdx.x;
    const int warp = tid >> 5;
    const int lane = tid & 31;
    const int g    = lane >> 2;
    const int q4   = lane & 3;

    const int it = gridDim.x - 1 - blockIdx.x;   // heavy tiles first
    const int bh = blockIdx.y;
    const int b = bh >> 4, h = bh & 15;
    const int i0 = it * 64;

    const size_t hoff = (size_t)b * NSEQ * DMODEL + h * DHEAD;
    const __half* qhb = qh + hoff;
    const __half* khb = kh + hoff;
    const __half* vhb = vh + hoff;

    auto copyTile = [&](const __half* src, int row0, uint32_t buf) {
#pragma unroll
        for (int i = 0; i < 8; i++) {
            int s = i * 128 + tid;
            uint32_t r = (uint32_t)(s >> 4), seg = (uint32_t)(s & 15);
            cp16(buf + swz(r, seg),
                 src + (size_t)(row0 + (int)r) * DMODEL + seg * 8);
        }
    };

    uint32_t K0 = sb, K1 = sb + ABUF_B, V0 = sb + 2u * ABUF_B, V1 = sb + 3u * ABUF_B;

    // stage Q in K1 (freed before jt=1 needs it), then KV(0)
    copyTile(qhb, i0, K1);
    CP_COMMIT();
    copyTile(khb, 0, K0);
    copyTile(vhb, 0, V0);
    CP_COMMIT();

    CP_WAIT(1);                 // Q done
    __syncthreads();

    const uint32_t lrow = (uint32_t)(lane & 15);
    const uint32_t lhl  = (uint32_t)(lane >> 4);
    uint32_t Qh4[8][4];
#pragma unroll
    for (int kk = 0; kk < 8; kk++) {
        uint32_t row = (uint32_t)(warp * 16) + lrow;
        uint32_t seg = (uint32_t)(kk * 2) + lhl;
        ldmx4(K1 + swz(row, seg), Qh4[kk][0], Qh4[kk][1], Qh4[kk][2], Qh4[kk][3]);
    }

    float m0 = -1e30f, m1 = -1e30f, l0 = 0.f, l1 = 0.f;
    float oa[16][4];
#pragma unroll
    for (int d = 0; d < 16; d++)
#pragma unroll
        for (int r = 0; r < 4; r++) oa[d][r] = 0.f;

    const int NJT = it + 1;

    for (int jt = 0; jt < NJT; jt++) {
        int stg = jt & 1;
        uint32_t kb = stg ? K1 : K0;
        uint32_t vb = stg ? V1 : V0;

        CP_WAIT(0);
        __syncthreads();        // all warps done with previous buffers / Q frags
        if (jt + 1 < NJT) {
            copyTile(khb, (jt + 1) * 64, stg ? K0 : K1);
            copyTile(vhb, (jt + 1) * 64, stg ? V0 : V1);
            CP_COMMIT();
        }

        // ===== S = Qh @ Kh^T =====
        float s[8][4];
#pragma unroll
        for (int nb = 0; nb < 8; nb++)
#pragma unroll
            for (int r = 0; r < 4; r++) s[nb][r] = 0.f;

#pragma unroll
        for (int kk = 0; kk < 8; kk++) {
#pragma unroll
            for (int np = 0; np < 4; np++) {
                uint32_t row = (uint32_t)(np * 16) + lrow;
                uint32_t seg = (uint32_t)(kk * 2) + lhl;
                uint32_t h0, h1, h2, h3;
                ldmx4(kb + swz(row, seg), h0, h1, h2, h3);
                int nb = np * 2;
                mma16816(s[nb][0], s[nb][1], s[nb][2], s[nb][3],
                         Qh4[kk][0], Qh4[kk][1], Qh4[kk][2], Qh4[kk][3], h0, h2);
                mma16816(s[nb + 1][0], s[nb + 1][1], s[nb + 1][2], s[nb + 1][3],
                         Qh4[kk][0], Qh4[kk][1], Qh4[kk][2], Qh4[kk][3], h1, h3);
            }
        }

        // causal mask on diagonal tile
        if (jt == it) {
            int r0 = warp * 16 + g;
            int r1 = r0 + 8;
#pragma unroll
            for (int nb = 0; nb < 8; nb++) {
                int c0 = nb * 8 + 2 * q4;
                if (c0 > r0)     s[nb][0] = -1e30f;
                if (c0 + 1 > r0) s[nb][1] = -1e30f;
                if (c0 > r1)     s[nb][2] = -1e30f;
                if (c0 + 1 > r1) s[nb][3] = -1e30f;
            }
        }

        // online softmax
        float mx0 = -1e30f, mx1 = -1e30f;
#pragma unroll
        for (int nb = 0; nb < 8; nb++) {
            mx0 = fmaxf(mx0, fmaxf(s[nb][0], s[nb][1]));
            mx1 = fmaxf(mx1, fmaxf(s[nb][2], s[nb][3]));
        }
        mx0 = fmaxf(mx0, __shfl_xor_sync(0xffffffffu, mx0, 1));
        mx0 = fmaxf(mx0, __shfl_xor_sync(0xffffffffu, mx0, 2));
        mx1 = fmaxf(mx1, __shfl_xor_sync(0xffffffffu, mx1, 1));
        mx1 = fmaxf(mx1, __shfl_xor_sync(0xffffffffu, mx1, 2));

        float m0n = fmaxf(m0, mx0), m1n = fmaxf(m1, mx1);
        float f0 = __expf(m0 - m0n), f1 = __expf(m1 - m1n);

        float sum0 = 0.f, sum1 = 0.f;
#pragma unroll
        for (int nb = 0; nb < 8; nb++) {
            s[nb][0] = __expf(s[nb][0] - m0n);
            s[nb][1] = __expf(s[nb][1] - m0n);
            s[nb][2] = __expf(s[nb][2] - m1n);
            s[nb][3] = __expf(s[nb][3] - m1n);
            sum0 += s[nb][0] + s[nb][1];
            sum1 += s[nb][2] + s[nb][3];
        }
        sum0 += __shfl_xor_sync(0xffffffffu, sum0, 1);
        sum0 += __shfl_xor_sync(0xffffffffu, sum0, 2);
        sum1 += __shfl_xor_sync(0xffffffffu, sum1, 1);
        sum1 += __shfl_xor_sync(0xffffffffu, sum1, 2);

        m0 = m0n; m1 = m1n;
        l0 = l0 * f0 + sum0;
        l1 = l1 * f1 + sum1;

#pragma unroll
        for (int d = 0; d < 16; d++) {
            oa[d][0] *= f0; oa[d][1] *= f0;
            oa[d][2] *= f1; oa[d][3] *= f1;
        }

        // P -> fp16 A-frags (hi only)
        uint32_t Ph[4][4];
#pragma unroll
        for (int kk2 = 0; kk2 < 4; kk2++) {
            int nb = 2 * kk2;
#pragma unroll
            for (int half = 0; half < 2; half++) {
                int src = nb + half;
                __half2 hA = __floats2half2_rn(s[src][0], s[src][1]);
                __half2 hB = __floats2half2_rn(s[src][2], s[src][3]);
                Ph[kk2][half * 2 + 0] = *(uint32_t*)&hA;
                Ph[kk2][half * 2 + 1] = *(uint32_t*)&hB;
            }
        }

        // ===== O += Ph @ Vh =====
#pragma unroll
        for (int kk2 = 0; kk2 < 4; kk2++) {
#pragma unroll
            for (int dp = 0; dp < 8; dp++) {
                uint32_t row = (uint32_t)(kk2 * 16) + lrow;
                uint32_t seg = (uint32_t)(dp * 2) + lhl;
                uint32_t h0, h1, h2, h3;
                ldmx4t(vb + swz(row, seg), h0, h1, h2, h3);
                int dnb = dp * 2;
                mma16816(oa[dnb][0], oa[dnb][1], oa[dnb][2], oa[dnb][3],
                         Ph[kk2][0], Ph[kk2][1], Ph[kk2][2], Ph[kk2][3], h0, h1);
                mma16816(oa[dnb + 1][0], oa[dnb + 1][1], oa[dnb + 1][2], oa[dnb + 1][3],
                         Ph[kk2][0], Ph[kk2][1], Ph[kk2][2], Ph[kk2][3], h2, h3);
            }
        }
    }

    // epilogue: normalize, store fp16 (hi only)
    float inv0 = 1.0f / l0, inv1 = 1.0f / l1;
    int r0 = i0 + warp * 16 + g;
    __half* ohb = oh + hoff;
#pragma unroll
    for (int dnb = 0; dnb < 16; dnb++) {
        int col = dnb * 8 + 2 * q4;
        __half2 h0 = __floats2half2_rn(oa[dnb][0] * inv0, oa[dnb][1] * inv0);
        __half2 h1 = __floats2half2_rn(oa[dnb][2] * inv1, oa[dnb][3] * inv1);
        *(__half2*)&ohb[(size_t)r0 * DMODEL + col] = h0;
        *(__half2*)&ohb[(size_t)(r0 + 8) * DMODEL + col] = h1;
    }
}

// ---------------------------------------------------------------------------
extern "C" void kernel_launch(void* const* d_in, const int* in_sizes, int n_in,
                              void* d_out, int out_size)
{
    const float* x  = (const float*)d_in[0];
    const float* Wq = (const float*)d_in[1];
    const float* bq = (const float*)d_in[2];
    const float* Wk = (const float*)d_in[3];
    const float* bk = (const float*)d_in[4];
    const float* Wv = (const float*)d_in[5];
    const float* bv = (const float*)d_in[6];
    const float* Wo = (const float*)d_in[7];
    const float* bo = (const float*)d_in[8];
    float* out = (float*)d_out;

    __half *xhi, *ahi, *qhh, *khh, *vhh;
    __half *wq, *wk, *wv, *wo;
    cudaGetSymbolAddress((void**)&xhi, g_xhi);
    cudaGetSymbolAddress((void**)&ahi, g_ahi);
    cudaGetSymbolAddress((void**)&qhh, g_qh);
    cudaGetSymbolAddress((void**)&khh, g_kh);
    cudaGetSymbolAddress((void**)&vhh, g_vh);
    cudaGetSymbolAddress((void**)&wq, g_wq);
    cudaGetSymbolAddress((void**)&wk, g_wk);
    cudaGetSymbolAddress((void**)&wv, g_wv);
    cudaGetSymbolAddress((void**)&wo, g_wo);

    cudaFuncSetAttribute(gemm_qkv, cudaFuncAttributeMaxDynamicSharedMemorySize, GEMM1_SMEM);
    cudaFuncSetAttribute(gemm_1p, cudaFuncAttributeMaxDynamicSharedMemorySize, GEMM1_SMEM);
    cudaFuncSetAttribute(flash_attn_mma, cudaFuncAttributeMaxDynamicSharedMemorySize, ATT_SMEM);

    // prep: convert x and weights (row-major preserved, no transpose)
    int n4x = ROWS * DMODEL / 4;
    cvt_kernel<<<(n4x + 255) / 256, 256>>>((const float4*)x, xhi, n4x);
    int n4w = DMODEL * DMODEL / 4;
    dim3 wgrid((n4w + 255) / 256, 4);
    cvt_w4<<<wgrid, 256>>>(Wq, Wk, Wv, Wo, wq, wk, wv, wo);

    // fused QKV projection (single pass) + rotary
    dim3 qkv_grid(3 * DMODEL / TN, ROWS / TM);   // (48, 32)
    gemm_qkv<<<qkv_grid, 256, GEMM1_SMEM>>>(xhi, wq, wk, wv,
                                            bq, bk, bv, qhh, khh, vhh);

    // tensor-core flash attention (3 CTAs/SM)
    dim3 attn_grid(NSEQ / 64, BATCH * HEADS);   // (32, 32)
    flash_attn_mma<<<attn_grid, 128, ATT_SMEM>>>(qhh, khh, vhh, ahi);

    // output projection (single pass)
    dim3 ggrid(DMODEL / TN, ROWS / TM);   // (16, 32)
    gemm_1p<<<ggrid, 256, GEMM1_SMEM>>>(ahi, wo, bo, out);
}